// round 12
// baseline (speedup 1.0000x reference)
#include <cuda_runtime.h>
#include <cuda_fp16.h>
#include <math_constants.h>
#include <cstdint>

#define DM 2048
#define TS 2048
#define NB 4
#define NHEADS 16
#define HD 128
#define MR (NB * TS)   // 8192 rows
#define NQKV (3 * DM)  // 6144

// Scratch (device-global: no allocations allowed in kernel_launch)
__device__ __half g_xh[MR * DM];
__device__ __half g_wh[4 * DM * DM];
__device__ __half g_qh[MR * DM];
__device__ __half g_kh[MR * DM];
__device__ __half g_vh[MR * DM];
__device__ __half g_ah[MR * DM];
__device__ float  g_bias3[NQKV];

// ===========================================================================
// helpers
// ===========================================================================
__device__ __forceinline__ uint32_t smem_u32(const void* p) {
    uint32_t a;
    asm("{ .reg .u64 t; cvta.to.shared.u64 t, %1; cvt.u32.u64 %0, t; }"
        : "=r"(a) : "l"(p));
    return a;
}

__device__ __forceinline__ void cpasync16(uint32_t s, const void* g) {
    asm volatile("cp.async.cg.shared.global [%0], [%1], 16;" :: "r"(s), "l"(g));
}
#define CP_COMMIT() asm volatile("cp.async.commit_group;" ::: "memory")
#define CP_WAIT(n)  asm volatile("cp.async.wait_group %0;" :: "n"(n) : "memory")

__device__ __forceinline__ void mma_f16(float* c, const uint32_t* a,
                                        const uint32_t* b) {
    asm volatile(
        "mma.sync.aligned.m16n8k16.row.col.f32.f16.f16.f32 "
        "{%0,%1,%2,%3}, {%4,%5,%6,%7}, {%8,%9}, {%0,%1,%2,%3};"
        : "+f"(c[0]), "+f"(c[1]), "+f"(c[2]), "+f"(c[3])
        : "r"(a[0]), "r"(a[1]), "r"(a[2]), "r"(a[3]), "r"(b[0]), "r"(b[1]));
}

__device__ __forceinline__ void ldsm_x4(uint32_t& r0, uint32_t& r1,
                                        uint32_t& r2, uint32_t& r3,
                                        uint32_t addr) {
    asm volatile(
        "ldmatrix.sync.aligned.m8n8.x4.shared.b16 {%0,%1,%2,%3}, [%4];"
        : "=r"(r0), "=r"(r1), "=r"(r2), "=r"(r3) : "r"(addr));
}

// ===========================================================================
// fp32 -> fp16 conversion (rne); merged 4-weight variant; bias concat
// ===========================================================================
__global__ void cvt_f2h_kernel(const float* __restrict__ in,
                               __half* __restrict__ out, int n4) {
    int i = blockIdx.x * blockDim.x + threadIdx.x;
    int stride = gridDim.x * blockDim.x;
    for (; i < n4; i += stride) {
        float4 v = ((const float4*)in)[i];
        __half2 h0 = __floats2half2_rn(v.x, v.y);
        __half2 h1 = __floats2half2_rn(v.z, v.w);
        uint2 o = {*(uint32_t*)&h0, *(uint32_t*)&h1};
        ((uint2*)out)[i] = o;
    }
}

__global__ void cvt4_f2h_kernel(const float* __restrict__ s0,
                                const float* __restrict__ s1,
                                const float* __restrict__ s2,
                                const float* __restrict__ s3,
                                __half* __restrict__ out, int seg4) {
    int i = blockIdx.x * blockDim.x + threadIdx.x;
    int stride = gridDim.x * blockDim.x;
    int total = 4 * seg4;
    for (; i < total; i += stride) {
        int which = i / seg4;
        int off = i - which * seg4;
        const float* src = (which == 0) ? s0 : (which == 1) ? s1
                         : (which == 2) ? s2 : s3;
        float4 v = ((const float4*)src)[off];
        __half2 h0 = __floats2half2_rn(v.x, v.y);
        __half2 h1 = __floats2half2_rn(v.z, v.w);
        uint2 o = {*(uint32_t*)&h0, *(uint32_t*)&h1};
        ((uint2*)out)[i] = o;
    }
}

__global__ void pack_bias_kernel(const float* __restrict__ a,
                                 const float* __restrict__ b,
                                 const float* __restrict__ c,
                                 float* __restrict__ o) {
    int i = blockIdx.x * blockDim.x + threadIdx.x;
    if (i < DM) {
        o[i] = a[i];
        o[i + DM] = b[i];
        o[i + 2 * DM] = c[i];
    }
}

// ===========================================================================
// fp16 mma.sync GEMM: C[M][col] = A[M][K] * W[col][K]^T + bias[col]
// Block tile 128x128, K-chunk 64 halves, 3-stage cp.async (108 KB smem),
// 128 threads (4 warps), warp tile 64x64, 2 CTAs/SM (256 thr/SM -> 255
// regs/thread available: 128-float accumulators fit with no spill).
// Per k16: 8 ldmatrix.x4 + 32 HMMA (0.25 loads/mma, 2x accum reuse).
// Rows padded to 72 halves (36 words; conflict-free ldmatrix phases).
// Fused QKV: epilogue selects output pointer by (bn >> 11).
// ===========================================================================
#define BM 128
#define BN 128
#define BKH 64
#define RSW 36                                  // row stride in 4B words
#define STAGE_WORDS ((BM + BN) * RSW)           // 9216
#define GEMM_SMEM (3 * STAGE_WORDS * 4)         // 110592
#define GTHREADS 128

__device__ __forceinline__ void load_chunk_h(const __half* __restrict__ A,
                                             const __half* __restrict__ W,
                                             uint32_t base, int slot,
                                             int bm, int bn, int k0, int tid) {
    uint32_t sa = base + slot * STAGE_WORDS * 4;
#pragma unroll
    for (int r = 0; r < 8; r++) {          // A: 128 rows x 8 x 16B
        int idx = r * GTHREADS + tid;
        int row = idx >> 3, q = idx & 7;
        cpasync16(sa + (row * RSW + q * 4) * 4,
                  A + (size_t)(bm + row) * DM + k0 + q * 8);
    }
    uint32_t sb = sa + BM * RSW * 4;
#pragma unroll
    for (int r = 0; r < 8; r++) {          // B: 128 rows x 8 x 16B
        int idx = r * GTHREADS + tid;
        int row = idx >> 3, q = idx & 7;
        cpasync16(sb + (row * RSW + q * 4) * 4,
                  W + (size_t)(bn + row) * DM + k0 + q * 8);
    }
    CP_COMMIT();
}

__global__ __launch_bounds__(GTHREADS, 2)
void gemm_f16_kernel(const __half* __restrict__ A,
                     const __half* __restrict__ W,
                     const float* __restrict__ bias,
                     void* __restrict__ C0,
                     void* __restrict__ C1,
                     void* __restrict__ C2,
                     int outHalf)
{
    extern __shared__ uint32_t smw[];

    const int tid = threadIdx.x;
    const int bm = blockIdx.y * BM;
    const int bn = blockIdx.x * BN;
    const int wid = tid >> 5;
    const int lane = tid & 31;
    const int wm = wid & 1;         // 0..1 : 64-row slice
    const int wn = wid >> 1;        // 0..1 : 64-col slice
    const int g = lane >> 2;
    const int tg = lane & 3;
    uint32_t base = smem_u32(smw);

    const int a_row = wm * 64 + ((lane >> 3) & 1) * 8 + (lane & 7);
    const int a_kw  = ((lane >> 4) & 1) * 4;
    const int b_row = wn * 64 + ((lane >> 4) & 1) * 8 + (lane & 7);
    const int b_kw  = ((lane >> 3) & 1) * 4;

    float c[4][8][4];
#pragma unroll
    for (int i = 0; i < 4; i++)
#pragma unroll
        for (int j = 0; j < 8; j++)
#pragma unroll
            for (int v = 0; v < 4; v++) c[i][j][v] = 0.f;

    load_chunk_h(A, W, base, 0, bm, bn, 0 * BKH, tid);
    load_chunk_h(A, W, base, 1, bm, bn, 1 * BKH, tid);
    load_chunk_h(A, W, base, 2, bm, bn, 2 * BKH, tid);
    CP_WAIT(2);
    __syncthreads();

    const int NCHUNK = DM / BKH;    // 32
    int slot = 0;
    for (int k = 0; k < NCHUNK; k++) {
        uint32_t Abase = base + slot * STAGE_WORDS * 4;
        uint32_t Bbase = Abase + BM * RSW * 4;

#pragma unroll
        for (int kw = 0; kw < 32; kw += 8) {   // four k16 steps (word offset)
            uint32_t a[4][4], b[8][2];
#pragma unroll
            for (int i = 0; i < 4; i++)
                ldsm_x4(a[i][0], a[i][1], a[i][2], a[i][3],
                        Abase + (uint32_t)(((a_row + i * 16) * RSW) + a_kw + kw) * 4);
#pragma unroll
            for (int jj = 0; jj < 4; jj++)
                ldsm_x4(b[2 * jj][0], b[2 * jj][1], b[2 * jj + 1][0], b[2 * jj + 1][1],
                        Bbase + (uint32_t)(((b_row + jj * 16) * RSW) + b_kw + kw) * 4);
#pragma unroll
            for (int i = 0; i < 4; i++)
#pragma unroll
                for (int j = 0; j < 8; j++)
                    mma_f16(c[i][j], a[i], b[j]);
        }

        if (k + 1 < NCHUNK) {
            __syncthreads();                 // all warps done reading this slot
            if (k + 3 < NCHUNK) {
                load_chunk_h(A, W, base, slot, bm, bn, (k + 3) * BKH, tid);
                CP_WAIT(2);
            } else if (k + 2 < NCHUNK) {
                CP_WAIT(1);
            } else {
                CP_WAIT(0);
            }
            __syncthreads();
        }
        slot = (slot == 2) ? 0 : slot + 1;
    }

    const int which = bn >> 11;
    void* Csel = (which == 0) ? C0 : ((which == 1) ? C1 : C2);

#pragma unroll
    for (int j = 0; j < 8; j++) {
        int col = bn + wn * 64 + j * 8 + 2 * tg;
        int coll = col & (DM - 1);
        float b0 = bias[col], b1 = bias[col + 1];
#pragma unroll
        for (int i = 0; i < 4; i++) {
            int row0 = bm + wm * 64 + i * 16 + g;
            float v00 = c[i][j][0] + b0, v01 = c[i][j][1] + b1;
            float v10 = c[i][j][2] + b0, v11 = c[i][j][3] + b1;
            if (outHalf) {
                __half* C = (__half*)Csel;
                __half2 h0 = __floats2half2_rn(v00, v01);
                __half2 h1 = __floats2half2_rn(v10, v11);
                *(__half2*)&C[(size_t)row0 * DM + coll] = h0;
                *(__half2*)&C[(size_t)(row0 + 8) * DM + coll] = h1;
            } else {
                float* C = (float*)Csel;
                *(float2*)&C[(size_t)row0 * DM + coll] = make_float2(v00, v01);
                *(float2*)&C[(size_t)(row0 + 8) * DM + coll] = make_float2(v10, v11);
            }
        }
    }
}

// ===========================================================================
// Tensor-core flash attention (fp16 mma.sync, fp32 softmax/accum).
// Round-11 winner: ldmatrix Q/K/Vt fragments, P register-resident.
// ===========================================================================
#define FQ 128
#define FK 64
#define QSW 68     // Q/K row stride in words (136 halves)
#define VSW 36     // Vt row stride in words (72 halves)

#define OFF_Q  0
#define OFF_K  (FQ * QSW)                    // 8704
#define OFF_VT (OFF_K + FK * QSW)            // 13056
#define OFF_MS (OFF_VT + HD * VSW)           // 17664
#define FLASH_SMEM_BYTES ((OFF_MS + 64) * 4) // 70912

__global__ __launch_bounds__(256, 1)
void flash_f16_kernel(const __half* __restrict__ Q, const __half* __restrict__ K,
                      const __half* __restrict__ V, const int* __restrict__ mask,
                      __half* __restrict__ O)
{
    extern __shared__ uint32_t smw[];
    uint32_t* Qs = smw + OFF_Q;
    uint32_t* Ks = smw + OFF_K;
    uint32_t* Vt = smw + OFF_VT;
    int*      msk = (int*)(smw + OFF_MS);
    __half*   VtH = (__half*)Vt;

    const int tid = threadIdx.x;
    const int wid = tid >> 5;
    const int lane = tid & 31;
    const int g = lane >> 2;
    const int tg = lane & 3;
    const int b = blockIdx.x >> 4;
    const int h = blockIdx.x & 15;
    const int q0 = blockIdx.y * FQ;
    const size_t base = (size_t)b * TS * DM + (size_t)h * HD;
    const float scale = 0.08838834764831845f;
    const int qr = wid * 16;

    const int a_mrow = ((lane >> 3) & 1) * 8 + (lane & 7);
    const int a_kw   = ((lane >> 4) & 1) * 4;
    const int b_nrow = ((lane >> 4) & 1) * 8 + (lane & 7);
    const int b_kw   = ((lane >> 3) & 1) * 4;

    const uint32_t Qbase  = smem_u32(Qs);
    const uint32_t Kbase  = smem_u32(Ks);
    const uint32_t Vtbase = smem_u32(Vt);

    for (int i = tid; i < FQ * (HD / 8); i += 256) {
        int r = i >> 4, c8 = i & 15;
        *(uint4*)&Qs[r * QSW + c8 * 4] =
            *(const uint4*)&Q[base + (size_t)(q0 + r) * DM + c8 * 8];
    }

    float m0 = -CUDART_INF_F, m1 = -CUDART_INF_F;
    float l0 = 0.f, l1 = 0.f;
    float co[16][4];
#pragma unroll
    for (int j = 0; j < 16; j++)
#pragma unroll
        for (int v = 0; v < 4; v++) co[j][v] = 0.f;

    for (int kt = 0; kt < TS / FK; kt++) {
        const int k0 = kt * FK;
        __syncthreads();

        for (int i = tid; i < FK * (HD / 8); i += 256) {
            int r = i >> 4, c8 = i & 15;
            *(uint4*)&Ks[r * QSW + c8 * 4] =
                *(const uint4*)&K[base + (size_t)(k0 + r) * DM + c8 * 8];
        }
        for (int i = tid; i < FK * (HD / 8); i += 256) {
            int r = i & 63, c8 = i >> 6;
            uint4 vv = *(const uint4*)&V[base + (size_t)(k0 + r) * DM + c8 * 8];
            const __half2* hp = (const __half2*)&vv;
            int c = c8 * 8;
#pragma unroll
            for (int t = 0; t < 4; t++) {
                VtH[(c + 2 * t + 0) * (2 * VSW) + r] = __low2half(hp[t]);
                VtH[(c + 2 * t + 1) * (2 * VSW) + r] = __high2half(hp[t]);
            }
        }
        if (tid < 64) msk[tid] = mask[b * TS + k0 + tid];
        __syncthreads();

        float cs[8][4];
#pragma unroll
        for (int j = 0; j < 8; j++)
#pragma unroll
            for (int v = 0; v < 4; v++) cs[j][v] = 0.f;

#pragma unroll
        for (int ks = 0; ks < 8; ks++) {
            int kw = ks * 8;
            uint32_t a[4], bb[8][2];
            ldsm_x4(a[0], a[1], a[2], a[3],
                    Qbase + (uint32_t)(((qr + a_mrow) * QSW) + a_kw + kw) * 4);
#pragma unroll
            for (int jj = 0; jj < 4; jj++)
                ldsm_x4(bb[2 * jj][0], bb[2 * jj][1],
                        bb[2 * jj + 1][0], bb[2 * jj + 1][1],
                        Kbase + (uint32_t)(((jj * 16 + b_nrow) * QSW) + b_kw + kw) * 4);
#pragma unroll
            for (int j = 0; j < 8; j++)
                mma_f16(cs[j], a, bb[j]);
        }

#pragma unroll
        for (int j = 0; j < 8; j++) {
            int c0 = j * 8 + 2 * tg;
            int mk0 = msk[c0], mk1 = msk[c0 + 1];
            cs[j][0] = mk0 ? cs[j][0] * scale : -CUDART_INF_F;
            cs[j][1] = mk1 ? cs[j][1] * scale : -CUDART_INF_F;
            cs[j][2] = mk0 ? cs[j][2] * scale : -CUDART_INF_F;
            cs[j][3] = mk1 ? cs[j][3] * scale : -CUDART_INF_F;
        }

        float mx0 = -CUDART_INF_F, mx1 = -CUDART_INF_F;
#pragma unroll
        for (int j = 0; j < 8; j++) {
            mx0 = fmaxf(mx0, fmaxf(cs[j][0], cs[j][1]));
            mx1 = fmaxf(mx1, fmaxf(cs[j][2], cs[j][3]));
        }
        mx0 = fmaxf(mx0, __shfl_xor_sync(0xffffffffu, mx0, 1));
        mx0 = fmaxf(mx0, __shfl_xor_sync(0xffffffffu, mx0, 2));
        mx1 = fmaxf(mx1, __shfl_xor_sync(0xffffffffu, mx1, 1));
        mx1 = fmaxf(mx1, __shfl_xor_sync(0xffffffffu, mx1, 2));

        float mn0 = fmaxf(m0, mx0), mn1 = fmaxf(m1, mx1);
        float corr0 = __expf(m0 - mn0), corr1 = __expf(m1 - mn1);
        m0 = mn0; m1 = mn1;

        uint32_t ph0[8], ph1[8];
        float rs0 = 0.f, rs1 = 0.f;
#pragma unroll
        for (int j = 0; j < 8; j++) {
            __half2 h0 = __floats2half2_rn(__expf(cs[j][0] - mn0),
                                           __expf(cs[j][1] - mn0));
            __half2 h1 = __floats2half2_rn(__expf(cs[j][2] - mn1),
                                           __expf(cs[j][3] - mn1));
            ph0[j] = *(uint32_t*)&h0;
            ph1[j] = *(uint32_t*)&h1;
            float2 f0 = __half22float2(h0);
            float2 f1 = __half22float2(h1);
            rs0 += f0.x + f0.y; rs1 += f1.x + f1.y;
        }
        rs0 += __shfl_xor_sync(0xffffffffu, rs0, 1);
        rs0 += __shfl_xor_sync(0xffffffffu, rs0, 2);
        rs1 += __shfl_xor_sync(0xffffffffu, rs1, 1);
        rs1 += __shfl_xor_sync(0xffffffffu, rs1, 2);
        l0 = l0 * corr0 + rs0;
        l1 = l1 * corr1 + rs1;

#pragma unroll
        for (int j = 0; j < 16; j++) {
            co[j][0] *= corr0; co[j][1] *= corr0;
            co[j][2] *= corr1; co[j][3] *= corr1;
        }

#pragma unroll
        for (int ks2 = 0; ks2 < 4; ks2++) {
            int kw = ks2 * 8;
            uint32_t a[4] = {ph0[2 * ks2], ph1[2 * ks2],
                             ph0[2 * ks2 + 1], ph1[2 * ks2 + 1]};
            uint32_t bb[16][2];
#pragma unroll
            for (int jj = 0; jj < 8; jj++)
                ldsm_x4(bb[2 * jj][0], bb[2 * jj][1],
                        bb[2 * jj + 1][0], bb[2 * jj + 1][1],
                        Vtbase + (uint32_t)(((jj * 16 + b_nrow) * VSW) + b_kw + kw) * 4);
#pragma unroll
            for (int j2 = 0; j2 < 16; j2++)
                mma_f16(co[j2], a, bb[j2]);
        }
    }

    float inv0 = 1.f / l0, inv1 = 1.f / l1;
    size_t r0 = (size_t)(q0 + qr + g);
    size_t r1 = r0 + 8;
#pragma unroll
    for (int j2 = 0; j2 < 16; j2++) {
        int col = j2 * 8 + 2 * tg;
        __half2 h0 = __floats2half2_rn(co[j2][0] * inv0, co[j2][1] * inv0);
        __half2 h1 = __floats2half2_rn(co[j2][2] * inv1, co[j2][3] * inv1);
        *(__half2*)&O[base + r0 * DM + col] = h0;
        *(__half2*)&O[base + r1 * DM + col] = h1;
    }
}

// ---------------------------------------------------------------------------
extern "C" void kernel_launch(void* const* d_in, const int* in_sizes, int n_in,
                              void* d_out, int out_size)
{
    const float* x  = (const float*)d_in[0];
    const int* mask = (const int*)d_in[1];
    const float* Wq = (const float*)d_in[2];
    const float* bq = (const float*)d_in[3];
    const float* Wk = (const float*)d_in[4];
    const float* bk = (const float*)d_in[5];
    const float* Wv = (const float*)d_in[6];
    const float* bv = (const float*)d_in[7];
    const float* Wo = (const float*)d_in[8];
    const float* bo = (const float*)d_in[9];
    float* out = (float*)d_out;

    __half *xh, *wh, *qh, *kh, *vh, *ah;
    float* bias3;
    cudaGetSymbolAddress((void**)&xh, g_xh);
    cudaGetSymbolAddress((void**)&wh, g_wh);
    cudaGetSymbolAddress((void**)&qh, g_qh);
    cudaGetSymbolAddress((void**)&kh, g_kh);
    cudaGetSymbolAddress((void**)&vh, g_vh);
    cudaGetSymbolAddress((void**)&ah, g_ah);
    cudaGetSymbolAddress((void**)&bias3, g_bias3);

    cudaFuncSetAttribute(gemm_f16_kernel,
                         cudaFuncAttributeMaxDynamicSharedMemorySize, GEMM_SMEM);
    cudaFuncSetAttribute(flash_f16_kernel,
                         cudaFuncAttributeMaxDynamicSharedMemorySize,
                         FLASH_SMEM_BYTES);

    const int NX4 = MR * DM / 4;
    const int NW4 = DM * DM / 4;

    // fp32 -> fp16 conversion (rne): x separate, 4 weights merged; bias concat
    cvt_f2h_kernel<<<2048, 256>>>(x, xh, NX4);
    cvt4_f2h_kernel<<<4096, 256>>>(Wq, Wk, Wv, Wo, wh, NW4);
    pack_bias_kernel<<<8, 256>>>(bq, bk, bv, bias3);

    // Fused QKV projection: N = 6144 over concatenated weights
    dim3 qkvgrid(NQKV / BN, MR / BM);  // (48, 64)
    gemm_f16_kernel<<<qkvgrid, GTHREADS, GEMM_SMEM>>>(
        xh, wh, bias3, qh, kh, vh, 1);

    flash_f16_kernel<<<dim3(NB * NHEADS, TS / FQ), 256, FLASH_SMEM_BYTES>>>(
        qh, kh, vh, mask, ah);

    // Final projection (float output)
    dim3 ogrid(DM / BN, MR / BM);      // (16, 64)
    gemm_f16_kernel<<<ogrid, GTHREADS, GEMM_SMEM>>>(
        ah, wh + 3 * (size_t)DM * DM, bo, out, nullptr, nullptr, 0);
}

// round 13
// speedup vs baseline: 1.0389x; 1.0389x over previous
#include <cuda_runtime.h>
#include <cuda_fp16.h>
#include <math_constants.h>
#include <cstdint>

#define DM 2048
#define TS 2048
#define NB 4
#define NHEADS 16
#define HD 128
#define MR (NB * TS)   // 8192 rows
#define NQKV (3 * DM)  // 6144

// Scratch (device-global: no allocations allowed in kernel_launch)
__device__ __half g_xh[MR * DM];
__device__ __half g_wh[4 * DM * DM];
__device__ __half g_qh[MR * DM];
__device__ __half g_kh[MR * DM];
__device__ __half g_vh[MR * DM];
__device__ __half g_ah[MR * DM];
__device__ float  g_bias3[NQKV];

// ===========================================================================
// helpers
// ===========================================================================
__device__ __forceinline__ uint32_t smem_u32(const void* p) {
    uint32_t a;
    asm("{ .reg .u64 t; cvta.to.shared.u64 t, %1; cvt.u32.u64 %0, t; }"
        : "=r"(a) : "l"(p));
    return a;
}

__device__ __forceinline__ void cpasync16(uint32_t s, const void* g) {
    asm volatile("cp.async.cg.shared.global [%0], [%1], 16;" :: "r"(s), "l"(g));
}
#define CP_COMMIT() asm volatile("cp.async.commit_group;" ::: "memory")
#define CP_WAIT(n)  asm volatile("cp.async.wait_group %0;" :: "n"(n) : "memory")

__device__ __forceinline__ void mma_f16(float* c, const uint32_t* a,
                                        const uint32_t* b) {
    asm volatile(
        "mma.sync.aligned.m16n8k16.row.col.f32.f16.f16.f32 "
        "{%0,%1,%2,%3}, {%4,%5,%6,%7}, {%8,%9}, {%0,%1,%2,%3};"
        : "+f"(c[0]), "+f"(c[1]), "+f"(c[2]), "+f"(c[3])
        : "r"(a[0]), "r"(a[1]), "r"(a[2]), "r"(a[3]), "r"(b[0]), "r"(b[1]));
}

__device__ __forceinline__ void ldsm_x4(uint32_t& r0, uint32_t& r1,
                                        uint32_t& r2, uint32_t& r3,
                                        uint32_t addr) {
    asm volatile(
        "ldmatrix.sync.aligned.m8n8.x4.shared.b16 {%0,%1,%2,%3}, [%4];"
        : "=r"(r0), "=r"(r1), "=r"(r2), "=r"(r3) : "r"(addr));
}

__device__ __forceinline__ void ldsm_x4_t(uint32_t& r0, uint32_t& r1,
                                          uint32_t& r2, uint32_t& r3,
                                          uint32_t addr) {
    asm volatile(
        "ldmatrix.sync.aligned.m8n8.x4.trans.shared.b16 {%0,%1,%2,%3}, [%4];"
        : "=r"(r0), "=r"(r1), "=r"(r2), "=r"(r3) : "r"(addr));
}

// ===========================================================================
// fp32 -> fp16 conversion (rne); bias concat
// ===========================================================================
__global__ void cvt_f2h_kernel(const float* __restrict__ in,
                               __half* __restrict__ out, int n4) {
    int i = blockIdx.x * blockDim.x + threadIdx.x;
    int stride = gridDim.x * blockDim.x;
    for (; i < n4; i += stride) {
        float4 v = ((const float4*)in)[i];
        __half2 h0 = __floats2half2_rn(v.x, v.y);
        __half2 h1 = __floats2half2_rn(v.z, v.w);
        uint2 o = {*(uint32_t*)&h0, *(uint32_t*)&h1};
        ((uint2*)out)[i] = o;
    }
}

__global__ void pack_bias_kernel(const float* __restrict__ a,
                                 const float* __restrict__ b,
                                 const float* __restrict__ c,
                                 float* __restrict__ o) {
    int i = blockIdx.x * blockDim.x + threadIdx.x;
    if (i < DM) {
        o[i] = a[i];
        o[i + DM] = b[i];
        o[i + 2 * DM] = c[i];
    }
}

// ===========================================================================
// fp16 mma.sync GEMM (Round-11 winner: ldmatrix fragments, 2 CTAs/SM).
// Block tile 128x128, K-chunk 64 halves, 3-stage cp.async (108 KB smem),
// 256 threads, warp tile 64x32. Fused QKV epilogue by (bn >> 11).
// ===========================================================================
#define BM 128
#define BN 128
#define BKH 64
#define RSW 36                                  // row stride in 4B words
#define STAGE_WORDS ((BM + BN) * RSW)           // 9216
#define GEMM_SMEM (3 * STAGE_WORDS * 4)         // 110592
#define GTHREADS 256

__device__ __forceinline__ void load_chunk_h(const __half* __restrict__ A,
                                             const __half* __restrict__ W,
                                             uint32_t base, int slot,
                                             int bm, int bn, int k0, int tid) {
    uint32_t sa = base + slot * STAGE_WORDS * 4;
#pragma unroll
    for (int r = 0; r < 4; r++) {          // A: 128 rows x 8 x 16B
        int idx = r * GTHREADS + tid;
        int row = idx >> 3, q = idx & 7;
        cpasync16(sa + (row * RSW + q * 4) * 4,
                  A + (size_t)(bm + row) * DM + k0 + q * 8);
    }
    uint32_t sb = sa + BM * RSW * 4;
#pragma unroll
    for (int r = 0; r < 4; r++) {          // B: 128 rows x 8 x 16B
        int idx = r * GTHREADS + tid;
        int row = idx >> 3, q = idx & 7;
        cpasync16(sb + (row * RSW + q * 4) * 4,
                  W + (size_t)(bn + row) * DM + k0 + q * 8);
    }
    CP_COMMIT();
}

__global__ __launch_bounds__(GTHREADS, 2)
void gemm_f16_kernel(const __half* __restrict__ A,
                     const __half* __restrict__ W,
                     const float* __restrict__ bias,
                     void* __restrict__ C0,
                     void* __restrict__ C1,
                     void* __restrict__ C2,
                     int outHalf)
{
    extern __shared__ uint32_t smw[];

    const int tid = threadIdx.x;
    const int bm = blockIdx.y * BM;
    const int bn = blockIdx.x * BN;
    const int wid = tid >> 5;
    const int lane = tid & 31;
    const int wm = wid & 1;
    const int wn = wid >> 1;
    const int g = lane >> 2;
    const int tg = lane & 3;
    uint32_t base = smem_u32(smw);

    const int a_row = wm * 64 + ((lane >> 3) & 1) * 8 + (lane & 7);
    const int a_kw  = ((lane >> 4) & 1) * 4;
    const int b_row = wn * 32 + ((lane >> 4) & 1) * 8 + (lane & 7);
    const int b_kw  = ((lane >> 3) & 1) * 4;

    float c[4][4][4];
#pragma unroll
    for (int i = 0; i < 4; i++)
#pragma unroll
        for (int j = 0; j < 4; j++)
#pragma unroll
            for (int v = 0; v < 4; v++) c[i][j][v] = 0.f;

    load_chunk_h(A, W, base, 0, bm, bn, 0 * BKH, tid);
    load_chunk_h(A, W, base, 1, bm, bn, 1 * BKH, tid);
    load_chunk_h(A, W, base, 2, bm, bn, 2 * BKH, tid);
    CP_WAIT(2);
    __syncthreads();

    const int NCHUNK = DM / BKH;    // 32
    int slot = 0;
    for (int k = 0; k < NCHUNK; k++) {
        uint32_t Abase = base + slot * STAGE_WORDS * 4;
        uint32_t Bbase = Abase + BM * RSW * 4;

#pragma unroll
        for (int kw = 0; kw < 32; kw += 8) {
            uint32_t a[4][4], b[4][2];
#pragma unroll
            for (int i = 0; i < 4; i++)
                ldsm_x4(a[i][0], a[i][1], a[i][2], a[i][3],
                        Abase + (uint32_t)(((a_row + i * 16) * RSW) + a_kw + kw) * 4);
#pragma unroll
            for (int jj = 0; jj < 2; jj++)
                ldsm_x4(b[2 * jj][0], b[2 * jj][1], b[2 * jj + 1][0], b[2 * jj + 1][1],
                        Bbase + (uint32_t)(((b_row + jj * 16) * RSW) + b_kw + kw) * 4);
#pragma unroll
            for (int i = 0; i < 4; i++)
#pragma unroll
                for (int j = 0; j < 4; j++)
                    mma_f16(c[i][j], a[i], b[j]);
        }

        if (k + 1 < NCHUNK) {
            __syncthreads();
            if (k + 3 < NCHUNK) {
                load_chunk_h(A, W, base, slot, bm, bn, (k + 3) * BKH, tid);
                CP_WAIT(2);
            } else if (k + 2 < NCHUNK) {
                CP_WAIT(1);
            } else {
                CP_WAIT(0);
            }
            __syncthreads();
        }
        slot = (slot == 2) ? 0 : slot + 1;
    }

    const int which = bn >> 11;
    void* Csel = (which == 0) ? C0 : ((which == 1) ? C1 : C2);

#pragma unroll
    for (int j = 0; j < 4; j++) {
        int col = bn + wn * 32 + j * 8 + 2 * tg;
        int coll = col & (DM - 1);
        float b0 = bias[col], b1 = bias[col + 1];
#pragma unroll
        for (int i = 0; i < 4; i++) {
            int row0 = bm + wm * 64 + i * 16 + g;
            float v00 = c[i][j][0] + b0, v01 = c[i][j][1] + b1;
            float v10 = c[i][j][2] + b0, v11 = c[i][j][3] + b1;
            if (outHalf) {
                __half* C = (__half*)Csel;
                __half2 h0 = __floats2half2_rn(v00, v01);
                __half2 h1 = __floats2half2_rn(v10, v11);
                *(__half2*)&C[(size_t)row0 * DM + coll] = h0;
                *(__half2*)&C[(size_t)(row0 + 8) * DM + coll] = h1;
            } else {
                float* C = (float*)Csel;
                *(float2*)&C[(size_t)row0 * DM + coll] = make_float2(v00, v01);
                *(float2*)&C[(size_t)(row0 + 8) * DM + coll] = make_float2(v10, v11);
            }
        }
    }
}

// ===========================================================================
// Tensor-core flash attention (fp16 mma.sync, fp32 softmax/accum).
// NEW: V stays ROW-MAJOR in smem (uint4 copy like K, zero scalar stores);
// PV B-fragments come directly from row-major V via ldmatrix.x4.trans.
// P register-resident; Q/K fragments via ldmatrix (Round-11 scheme).
// ===========================================================================
#define FQ 128
#define FK 64
#define QSW 68     // Q/K/V row stride in words (136 halves)

#define OFF_Q  0
#define OFF_K  (FQ * QSW)                    // 8704
#define OFF_V  (OFF_K + FK * QSW)            // 13056
#define OFF_MS (OFF_V + FK * QSW)            // 17408
#define FLASH_SMEM_BYTES ((OFF_MS + 64) * 4) // 69888

__global__ __launch_bounds__(256, 1)
void flash_f16_kernel(const __half* __restrict__ Q, const __half* __restrict__ K,
                      const __half* __restrict__ V, const int* __restrict__ mask,
                      __half* __restrict__ O)
{
    extern __shared__ uint32_t smw[];
    uint32_t* Qs = smw + OFF_Q;
    uint32_t* Ks = smw + OFF_K;
    uint32_t* Vs = smw + OFF_V;
    int*      msk = (int*)(smw + OFF_MS);

    const int tid = threadIdx.x;
    const int wid = tid >> 5;
    const int lane = tid & 31;
    const int g = lane >> 2;
    const int tg = lane & 3;
    const int b = blockIdx.x >> 4;
    const int h = blockIdx.x & 15;
    const int q0 = blockIdx.y * FQ;
    const size_t base = (size_t)b * TS * DM + (size_t)h * HD;
    const float scale = 0.08838834764831845f;
    const int qr = wid * 16;

    // ldmatrix lane-source rows/offsets
    const int a_mrow = ((lane >> 3) & 1) * 8 + (lane & 7);   // Q (non-trans)
    const int a_kw   = ((lane >> 4) & 1) * 4;
    const int b_nrow = ((lane >> 4) & 1) * 8 + (lane & 7);   // K (non-trans)
    const int b_kw   = ((lane >> 3) & 1) * 4;
    const int v_row  = ((lane >> 3) & 1) * 8 + (lane & 7);   // V (trans): key row
    const int v_cw   = ((lane >> 4) & 1) * 4;                // V: d col words

    const uint32_t Qbase = smem_u32(Qs);
    const uint32_t Kbase = smem_u32(Ks);
    const uint32_t Vbase = smem_u32(Vs);

    // Load Q tile [128][128] halves, row stride 68 words
    for (int i = tid; i < FQ * (HD / 8); i += 256) {
        int r = i >> 4, c8 = i & 15;
        *(uint4*)&Qs[r * QSW + c8 * 4] =
            *(const uint4*)&Q[base + (size_t)(q0 + r) * DM + c8 * 8];
    }

    float m0 = -CUDART_INF_F, m1 = -CUDART_INF_F;
    float l0 = 0.f, l1 = 0.f;
    float co[16][4];
#pragma unroll
    for (int j = 0; j < 16; j++)
#pragma unroll
        for (int v = 0; v < 4; v++) co[j][v] = 0.f;

    for (int kt = 0; kt < TS / FK; kt++) {
        const int k0 = kt * FK;
        __syncthreads();

        // K and V tiles [64][128] halves, both row-major (coalesced uint4)
        for (int i = tid; i < FK * (HD / 8); i += 256) {
            int r = i >> 4, c8 = i & 15;
            *(uint4*)&Ks[r * QSW + c8 * 4] =
                *(const uint4*)&K[base + (size_t)(k0 + r) * DM + c8 * 8];
        }
        for (int i = tid; i < FK * (HD / 8); i += 256) {
            int r = i >> 4, c8 = i & 15;
            *(uint4*)&Vs[r * QSW + c8 * 4] =
                *(const uint4*)&V[base + (size_t)(k0 + r) * DM + c8 * 8];
        }
        if (tid < 64) msk[tid] = mask[b * TS + k0 + tid];
        __syncthreads();

        // S = Q . K^T  (ldmatrix fragments)
        float cs[8][4];
#pragma unroll
        for (int j = 0; j < 8; j++)
#pragma unroll
            for (int v = 0; v < 4; v++) cs[j][v] = 0.f;

#pragma unroll
        for (int ks = 0; ks < 8; ks++) {
            int kw = ks * 8;
            uint32_t a[4], bb[8][2];
            ldsm_x4(a[0], a[1], a[2], a[3],
                    Qbase + (uint32_t)(((qr + a_mrow) * QSW) + a_kw + kw) * 4);
#pragma unroll
            for (int jj = 0; jj < 4; jj++)
                ldsm_x4(bb[2 * jj][0], bb[2 * jj][1],
                        bb[2 * jj + 1][0], bb[2 * jj + 1][1],
                        Kbase + (uint32_t)(((jj * 16 + b_nrow) * QSW) + b_kw + kw) * 4);
#pragma unroll
            for (int j = 0; j < 8; j++)
                mma_f16(cs[j], a, bb[j]);
        }

        // scale + mask
#pragma unroll
        for (int j = 0; j < 8; j++) {
            int c0 = j * 8 + 2 * tg;
            int mk0 = msk[c0], mk1 = msk[c0 + 1];
            cs[j][0] = mk0 ? cs[j][0] * scale : -CUDART_INF_F;
            cs[j][1] = mk1 ? cs[j][1] * scale : -CUDART_INF_F;
            cs[j][2] = mk0 ? cs[j][2] * scale : -CUDART_INF_F;
            cs[j][3] = mk1 ? cs[j][3] * scale : -CUDART_INF_F;
        }

        // row max (rows qr+g, qr+g+8); reduce over tg lanes
        float mx0 = -CUDART_INF_F, mx1 = -CUDART_INF_F;
#pragma unroll
        for (int j = 0; j < 8; j++) {
            mx0 = fmaxf(mx0, fmaxf(cs[j][0], cs[j][1]));
            mx1 = fmaxf(mx1, fmaxf(cs[j][2], cs[j][3]));
        }
        mx0 = fmaxf(mx0, __shfl_xor_sync(0xffffffffu, mx0, 1));
        mx0 = fmaxf(mx0, __shfl_xor_sync(0xffffffffu, mx0, 2));
        mx1 = fmaxf(mx1, __shfl_xor_sync(0xffffffffu, mx1, 1));
        mx1 = fmaxf(mx1, __shfl_xor_sync(0xffffffffu, mx1, 2));

        float mn0 = fmaxf(m0, mx0), mn1 = fmaxf(m1, mx1);
        float corr0 = __expf(m0 - mn0), corr1 = __expf(m1 - mn1);
        m0 = mn0; m1 = mn1;

        // P = exp(s-m) -> half(rne), register-resident PV A-fragments
        uint32_t ph0[8], ph1[8];
        float rs0 = 0.f, rs1 = 0.f;
#pragma unroll
        for (int j = 0; j < 8; j++) {
            __half2 h0 = __floats2half2_rn(__expf(cs[j][0] - mn0),
                                           __expf(cs[j][1] - mn0));
            __half2 h1 = __floats2half2_rn(__expf(cs[j][2] - mn1),
                                           __expf(cs[j][3] - mn1));
            ph0[j] = *(uint32_t*)&h0;
            ph1[j] = *(uint32_t*)&h1;
            float2 f0 = __half22float2(h0);
            float2 f1 = __half22float2(h1);
            rs0 += f0.x + f0.y; rs1 += f1.x + f1.y;
        }
        rs0 += __shfl_xor_sync(0xffffffffu, rs0, 1);
        rs0 += __shfl_xor_sync(0xffffffffu, rs0, 2);
        rs1 += __shfl_xor_sync(0xffffffffu, rs1, 1);
        rs1 += __shfl_xor_sync(0xffffffffu, rs1, 2);
        l0 = l0 * corr0 + rs0;
        l1 = l1 * corr1 + rs1;

#pragma unroll
        for (int j = 0; j < 16; j++) {
            co[j][0] *= corr0; co[j][1] *= corr0;
            co[j][2] *= corr1; co[j][3] *= corr1;
        }

        // O += P . V : B-fragments straight from row-major V via ldmatrix.trans
        // x4 matrices: {keys+0-7/d0-7, keys+8-15/d0-7, keys+0-7/d8-15, +8-15/d8-15}
        // -> transposed == non-trans load of Vt, so {r0,r1}=n-tile 2jj, {r2,r3}=2jj+1
#pragma unroll
        for (int ks2 = 0; ks2 < 4; ks2++) {
            uint32_t a[4] = {ph0[2 * ks2], ph1[2 * ks2],
                             ph0[2 * ks2 + 1], ph1[2 * ks2 + 1]};
            uint32_t bb[16][2];
#pragma unroll
            for (int jj = 0; jj < 8; jj++)
                ldsm_x4_t(bb[2 * jj][0], bb[2 * jj][1],
                          bb[2 * jj + 1][0], bb[2 * jj + 1][1],
                          Vbase + (uint32_t)(((ks2 * 16 + v_row) * QSW) + jj * 8 + v_cw) * 4);
#pragma unroll
            for (int j2 = 0; j2 < 16; j2++)
                mma_f16(co[j2], a, bb[j2]);
        }
    }

    // Epilogue: normalize, store half
    float inv0 = 1.f / l0, inv1 = 1.f / l1;
    size_t r0 = (size_t)(q0 + qr + g);
    size_t r1 = r0 + 8;
#pragma unroll
    for (int j2 = 0; j2 < 16; j2++) {
        int col = j2 * 8 + 2 * tg;
        __half2 h0 = __floats2half2_rn(co[j2][0] * inv0, co[j2][1] * inv0);
        __half2 h1 = __floats2half2_rn(co[j2][2] * inv1, co[j2][3] * inv1);
        *(__half2*)&O[base + r0 * DM + col] = h0;
        *(__half2*)&O[base + r1 * DM + col] = h1;
    }
}

// ---------------------------------------------------------------------------
extern "C" void kernel_launch(void* const* d_in, const int* in_sizes, int n_in,
                              void* d_out, int out_size)
{
    const float* x  = (const float*)d_in[0];
    const int* mask = (const int*)d_in[1];
    const float* Wq = (const float*)d_in[2];
    const float* bq = (const float*)d_in[3];
    const float* Wk = (const float*)d_in[4];
    const float* bk = (const float*)d_in[5];
    const float* Wv = (const float*)d_in[6];
    const float* bv = (const float*)d_in[7];
    const float* Wo = (const float*)d_in[8];
    const float* bo = (const float*)d_in[9];
    float* out = (float*)d_out;

    __half *xh, *wh, *qh, *kh, *vh, *ah;
    float* bias3;
    cudaGetSymbolAddress((void**)&xh, g_xh);
    cudaGetSymbolAddress((void**)&wh, g_wh);
    cudaGetSymbolAddress((void**)&qh, g_qh);
    cudaGetSymbolAddress((void**)&kh, g_kh);
    cudaGetSymbolAddress((void**)&vh, g_vh);
    cudaGetSymbolAddress((void**)&ah, g_ah);
    cudaGetSymbolAddress((void**)&bias3, g_bias3);

    cudaFuncSetAttribute(gemm_f16_kernel,
                         cudaFuncAttributeMaxDynamicSharedMemorySize, GEMM_SMEM);
    cudaFuncSetAttribute(flash_f16_kernel,
                         cudaFuncAttributeMaxDynamicSharedMemorySize,
                         FLASH_SMEM_BYTES);

    const int NX4 = MR * DM / 4;
    const int NW4 = DM * DM / 4;

    // fp32 -> fp16 conversion (rne); bias concat
    cvt_f2h_kernel<<<2048, 256>>>(x,  xh, NX4);
    cvt_f2h_kernel<<<1024, 256>>>(Wq, wh + 0 * (size_t)DM * DM, NW4);
    cvt_f2h_kernel<<<1024, 256>>>(Wk, wh + 1 * (size_t)DM * DM, NW4);
    cvt_f2h_kernel<<<1024, 256>>>(Wv, wh + 2 * (size_t)DM * DM, NW4);
    cvt_f2h_kernel<<<1024, 256>>>(Wo, wh + 3 * (size_t)DM * DM, NW4);
    pack_bias_kernel<<<8, 256>>>(bq, bk, bv, bias3);

    // Fused QKV projection: N = 6144 over concatenated weights
    dim3 qkvgrid(NQKV / BN, MR / BM);  // (48, 64)
    gemm_f16_kernel<<<qkvgrid, GTHREADS, GEMM_SMEM>>>(
        xh, wh, bias3, qh, kh, vh, 1);

    flash_f16_kernel<<<dim3(NB * NHEADS, TS / FQ), 256, FLASH_SMEM_BYTES>>>(
        qh, kh, vh, mask, ah);

    // Final projection (float output)
    dim3 ogrid(DM / BN, MR / BM);      // (16, 64)
    gemm_f16_kernel<<<ogrid, GTHREADS, GEMM_SMEM>>>(
        ah, wh + 3 * (size_t)DM * DM, bo, out, nullptr, nullptr, 0);
}

// round 14
// speedup vs baseline: 1.4853x; 1.4297x over previous
#include <cuda_runtime.h>
#include <cuda_fp16.h>
#include <math_constants.h>
#include <cstdint>

#define DM 2048
#define TS 2048
#define NB 4
#define NHEADS 16
#define HD 128
#define MR (NB * TS)   // 8192 rows
#define NQKV (3 * DM)  // 6144

// Scratch (device-global: no allocations allowed in kernel_launch)
__device__ __half g_xh[MR * DM];
__device__ __half g_wh[4 * DM * DM];
__device__ __half g_qh[MR * DM];
__device__ __half g_kh[MR * DM];
__device__ __half g_vh[MR * DM];
__device__ __half g_ah[MR * DM];
__device__ float  g_bias3[NQKV];

// ===========================================================================
// helpers
// ===========================================================================
__device__ __forceinline__ uint32_t smem_u32(const void* p) {
    uint32_t a;
    asm("{ .reg .u64 t; cvta.to.shared.u64 t, %1; cvt.u32.u64 %0, t; }"
        : "=r"(a) : "l"(p));
    return a;
}

__device__ __forceinline__ void cpasync16(uint32_t s, const void* g) {
    asm volatile("cp.async.cg.shared.global [%0], [%1], 16;" :: "r"(s), "l"(g));
}
#define CP_COMMIT() asm volatile("cp.async.commit_group;" ::: "memory")
#define CP_WAIT(n)  asm volatile("cp.async.wait_group %0;" :: "n"(n) : "memory")

__device__ __forceinline__ void mma_f16(float* c, const uint32_t* a,
                                        const uint32_t* b) {
    asm volatile(
        "mma.sync.aligned.m16n8k16.row.col.f32.f16.f16.f32 "
        "{%0,%1,%2,%3}, {%4,%5,%6,%7}, {%8,%9}, {%0,%1,%2,%3};"
        : "+f"(c[0]), "+f"(c[1]), "+f"(c[2]), "+f"(c[3])
        : "r"(a[0]), "r"(a[1]), "r"(a[2]), "r"(a[3]), "r"(b[0]), "r"(b[1]));
}

__device__ __forceinline__ void ldsm_x4(uint32_t& r0, uint32_t& r1,
                                        uint32_t& r2, uint32_t& r3,
                                        uint32_t addr) {
    asm volatile(
        "ldmatrix.sync.aligned.m8n8.x4.shared.b16 {%0,%1,%2,%3}, [%4];"
        : "=r"(r0), "=r"(r1), "=r"(r2), "=r"(r3) : "r"(addr));
}

__device__ __forceinline__ void ldsm_x4_t(uint32_t& r0, uint32_t& r1,
                                          uint32_t& r2, uint32_t& r3,
                                          uint32_t addr) {
    asm volatile(
        "ldmatrix.sync.aligned.m8n8.x4.trans.shared.b16 {%0,%1,%2,%3}, [%4];"
        : "=r"(r0), "=r"(r1), "=r"(r2), "=r"(r3) : "r"(addr));
}

// ===========================================================================
// fp32 -> fp16 conversion (rne); bias concat
// ===========================================================================
__global__ void cvt_f2h_kernel(const float* __restrict__ in,
                               __half* __restrict__ out, int n4) {
    int i = blockIdx.x * blockDim.x + threadIdx.x;
    int stride = gridDim.x * blockDim.x;
    for (; i < n4; i += stride) {
        float4 v = ((const float4*)in)[i];
        __half2 h0 = __floats2half2_rn(v.x, v.y);
        __half2 h1 = __floats2half2_rn(v.z, v.w);
        uint2 o = {*(uint32_t*)&h0, *(uint32_t*)&h1};
        ((uint2*)out)[i] = o;
    }
}

__global__ void pack_bias_kernel(const float* __restrict__ a,
                                 const float* __restrict__ b,
                                 const float* __restrict__ c,
                                 float* __restrict__ o) {
    int i = blockIdx.x * blockDim.x + threadIdx.x;
    if (i < DM) {
        o[i] = a[i];
        o[i + DM] = b[i];
        o[i + 2 * DM] = c[i];
    }
}

// ===========================================================================
// fp16 mma.sync GEMM (Round-11 winner: ldmatrix fragments, 2 CTAs/SM).
// Block tile 128x128, K-chunk 64 halves, 3-stage cp.async (108 KB smem),
// 256 threads, warp tile 64x32. Fused QKV epilogue by (bn >> 11).
// ===========================================================================
#define BM 128
#define BN 128
#define BKH 64
#define RSW 36                                  // row stride in 4B words
#define STAGE_WORDS ((BM + BN) * RSW)           // 9216
#define GEMM_SMEM (3 * STAGE_WORDS * 4)         // 110592
#define GTHREADS 256

__device__ __forceinline__ void load_chunk_h(const __half* __restrict__ A,
                                             const __half* __restrict__ W,
                                             uint32_t base, int slot,
                                             int bm, int bn, int k0, int tid) {
    uint32_t sa = base + slot * STAGE_WORDS * 4;
#pragma unroll
    for (int r = 0; r < 4; r++) {          // A: 128 rows x 8 x 16B
        int idx = r * GTHREADS + tid;
        int row = idx >> 3, q = idx & 7;
        cpasync16(sa + (row * RSW + q * 4) * 4,
                  A + (size_t)(bm + row) * DM + k0 + q * 8);
    }
    uint32_t sb = sa + BM * RSW * 4;
#pragma unroll
    for (int r = 0; r < 4; r++) {          // B: 128 rows x 8 x 16B
        int idx = r * GTHREADS + tid;
        int row = idx >> 3, q = idx & 7;
        cpasync16(sb + (row * RSW + q * 4) * 4,
                  W + (size_t)(bn + row) * DM + k0 + q * 8);
    }
    CP_COMMIT();
}

__global__ __launch_bounds__(GTHREADS, 2)
void gemm_f16_kernel(const __half* __restrict__ A,
                     const __half* __restrict__ W,
                     const float* __restrict__ bias,
                     void* __restrict__ C0,
                     void* __restrict__ C1,
                     void* __restrict__ C2,
                     int outHalf)
{
    extern __shared__ uint32_t smw[];

    const int tid = threadIdx.x;
    const int bm = blockIdx.y * BM;
    const int bn = blockIdx.x * BN;
    const int wid = tid >> 5;
    const int lane = tid & 31;
    const int wm = wid & 1;
    const int wn = wid >> 1;
    const int g = lane >> 2;
    const int tg = lane & 3;
    uint32_t base = smem_u32(smw);

    const int a_row = wm * 64 + ((lane >> 3) & 1) * 8 + (lane & 7);
    const int a_kw  = ((lane >> 4) & 1) * 4;
    const int b_row = wn * 32 + ((lane >> 4) & 1) * 8 + (lane & 7);
    const int b_kw  = ((lane >> 3) & 1) * 4;

    float c[4][4][4];
#pragma unroll
    for (int i = 0; i < 4; i++)
#pragma unroll
        for (int j = 0; j < 4; j++)
#pragma unroll
            for (int v = 0; v < 4; v++) c[i][j][v] = 0.f;

    load_chunk_h(A, W, base, 0, bm, bn, 0 * BKH, tid);
    load_chunk_h(A, W, base, 1, bm, bn, 1 * BKH, tid);
    load_chunk_h(A, W, base, 2, bm, bn, 2 * BKH, tid);
    CP_WAIT(2);
    __syncthreads();

    const int NCHUNK = DM / BKH;    // 32
    int slot = 0;
    for (int k = 0; k < NCHUNK; k++) {
        uint32_t Abase = base + slot * STAGE_WORDS * 4;
        uint32_t Bbase = Abase + BM * RSW * 4;

#pragma unroll
        for (int kw = 0; kw < 32; kw += 8) {
            uint32_t a[4][4], b[4][2];
#pragma unroll
            for (int i = 0; i < 4; i++)
                ldsm_x4(a[i][0], a[i][1], a[i][2], a[i][3],
                        Abase + (uint32_t)(((a_row + i * 16) * RSW) + a_kw + kw) * 4);
#pragma unroll
            for (int jj = 0; jj < 2; jj++)
                ldsm_x4(b[2 * jj][0], b[2 * jj][1], b[2 * jj + 1][0], b[2 * jj + 1][1],
                        Bbase + (uint32_t)(((b_row + jj * 16) * RSW) + b_kw + kw) * 4);
#pragma unroll
            for (int i = 0; i < 4; i++)
#pragma unroll
                for (int j = 0; j < 4; j++)
                    mma_f16(c[i][j], a[i], b[j]);
        }

        if (k + 1 < NCHUNK) {
            __syncthreads();
            if (k + 3 < NCHUNK) {
                load_chunk_h(A, W, base, slot, bm, bn, (k + 3) * BKH, tid);
                CP_WAIT(2);
            } else if (k + 2 < NCHUNK) {
                CP_WAIT(1);
            } else {
                CP_WAIT(0);
            }
            __syncthreads();
        }
        slot = (slot == 2) ? 0 : slot + 1;
    }

    const int which = bn >> 11;
    void* Csel = (which == 0) ? C0 : ((which == 1) ? C1 : C2);

#pragma unroll
    for (int j = 0; j < 4; j++) {
        int col = bn + wn * 32 + j * 8 + 2 * tg;
        int coll = col & (DM - 1);
        float b0 = bias[col], b1 = bias[col + 1];
#pragma unroll
        for (int i = 0; i < 4; i++) {
            int row0 = bm + wm * 64 + i * 16 + g;
            float v00 = c[i][j][0] + b0, v01 = c[i][j][1] + b1;
            float v10 = c[i][j][2] + b0, v11 = c[i][j][3] + b1;
            if (outHalf) {
                __half* C = (__half*)Csel;
                __half2 h0 = __floats2half2_rn(v00, v01);
                __half2 h1 = __floats2half2_rn(v10, v11);
                *(__half2*)&C[(size_t)row0 * DM + coll] = h0;
                *(__half2*)&C[(size_t)(row0 + 8) * DM + coll] = h1;
            } else {
                float* C = (float*)Csel;
                *(float2*)&C[(size_t)row0 * DM + coll] = make_float2(v00, v01);
                *(float2*)&C[(size_t)(row0 + 8) * DM + coll] = make_float2(v10, v11);
            }
        }
    }
}

// ===========================================================================
// Tensor-core flash attention (fp16 mma.sync, fp32 softmax/accum).
// NEW: cp.async DOUBLE-BUFFERED K/V tiles (load of tile kt+1 overlaps the
// whole compute of tile kt); mask row loaded once in the prologue; Q staged
// via cp.async. V row-major + ldmatrix.trans; P register-resident.
// ===========================================================================
#define FQ 128
#define FK 64
#define QSW 68                       // Q/K/V row stride in words (136 halves)
#define TILE_WORDS (FK * QSW)        // 4352

#define OFF_Q   0
#define OFF_KV  (FQ * QSW)                       // 8704
#define OFF_MSK (OFF_KV + 4 * TILE_WORDS)        // 26112
#define FLASH_SMEM_BYTES ((OFF_MSK + TS) * 4)    // 112640

__device__ __forceinline__ void flash_load_kv(const __half* __restrict__ K,
                                              const __half* __restrict__ V,
                                              uint32_t kvbase, int buf,
                                              size_t base, int k0, int tid) {
    uint32_t kb = kvbase + buf * 2 * TILE_WORDS * 4;
    uint32_t vb = kb + TILE_WORDS * 4;
#pragma unroll
    for (int r = 0; r < 4; r++) {        // K: 64 rows x 16 x 16B
        int idx = r * 256 + tid;
        int row = idx >> 4, q = idx & 15;
        cpasync16(kb + (row * QSW + q * 4) * 4,
                  K + base + (size_t)(k0 + row) * DM + q * 8);
    }
#pragma unroll
    for (int r = 0; r < 4; r++) {        // V: 64 rows x 16 x 16B
        int idx = r * 256 + tid;
        int row = idx >> 4, q = idx & 15;
        cpasync16(vb + (row * QSW + q * 4) * 4,
                  V + base + (size_t)(k0 + row) * DM + q * 8);
    }
    CP_COMMIT();
}

__global__ __launch_bounds__(256, 1)
void flash_f16_kernel(const __half* __restrict__ Q, const __half* __restrict__ K,
                      const __half* __restrict__ V, const int* __restrict__ mask,
                      __half* __restrict__ O)
{
    extern __shared__ uint32_t smw[];
    uint32_t* Qs = smw + OFF_Q;
    int*      msk = (int*)(smw + OFF_MSK);

    const int tid = threadIdx.x;
    const int wid = tid >> 5;
    const int lane = tid & 31;
    const int g = lane >> 2;
    const int tg = lane & 3;
    const int b = blockIdx.x >> 4;
    const int h = blockIdx.x & 15;
    const int q0 = blockIdx.y * FQ;
    const size_t base = (size_t)b * TS * DM + (size_t)h * HD;
    const float scale = 0.08838834764831845f;
    const int qr = wid * 16;

    // ldmatrix lane-source rows/offsets
    const int a_mrow = ((lane >> 3) & 1) * 8 + (lane & 7);   // Q (non-trans)
    const int a_kw   = ((lane >> 4) & 1) * 4;
    const int b_nrow = ((lane >> 4) & 1) * 8 + (lane & 7);   // K (non-trans)
    const int b_kw   = ((lane >> 3) & 1) * 4;
    const int v_row  = ((lane >> 3) & 1) * 8 + (lane & 7);   // V (trans): key row
    const int v_cw   = ((lane >> 4) & 1) * 4;                // V: d col words

    const uint32_t Qbase  = smem_u32(Qs);
    const uint32_t KVbase = smem_u32(smw + OFF_KV);

    // Prologue: Q via cp.async (128 rows x 16 x 16B = 8/thread)
#pragma unroll
    for (int r = 0; r < 8; r++) {
        int idx = r * 256 + tid;
        int row = idx >> 4, q = idx & 15;
        cpasync16(Qbase + (uint32_t)(row * QSW + q * 4) * 4,
                  Q + base + (size_t)(q0 + row) * DM + q * 8);
    }
    CP_COMMIT();
    // K/V tile 0 into buffer 0
    flash_load_kv(K, V, KVbase, 0, base, 0, tid);
    // mask row once
    for (int i = tid; i < TS; i += 256) msk[i] = mask[b * TS + i];

    float m0 = -CUDART_INF_F, m1 = -CUDART_INF_F;
    float l0 = 0.f, l1 = 0.f;
    float co[16][4];
#pragma unroll
    for (int j = 0; j < 16; j++)
#pragma unroll
        for (int v = 0; v < 4; v++) co[j][v] = 0.f;

    const int NT = TS / FK;   // 32
    for (int kt = 0; kt < NT; kt++) {
        const int k0 = kt * FK;
        // issue next tile's load (into the buffer last read at kt-1)
        if (kt + 1 < NT)
            flash_load_kv(K, V, KVbase, (kt + 1) & 1, base, k0 + FK, tid);
        if (kt + 1 < NT) { CP_WAIT(1); } else { CP_WAIT(0); }
        __syncthreads();                 // tile kt ready for all warps

        const uint32_t Kbase = KVbase + (uint32_t)((kt & 1) * 2 * TILE_WORDS) * 4;
        const uint32_t Vbase = Kbase + (uint32_t)TILE_WORDS * 4;

        // S = Q . K^T
        float cs[8][4];
#pragma unroll
        for (int j = 0; j < 8; j++)
#pragma unroll
            for (int v = 0; v < 4; v++) cs[j][v] = 0.f;

#pragma unroll
        for (int ks = 0; ks < 8; ks++) {
            int kw = ks * 8;
            uint32_t a[4], bb[8][2];
            ldsm_x4(a[0], a[1], a[2], a[3],
                    Qbase + (uint32_t)(((qr + a_mrow) * QSW) + a_kw + kw) * 4);
#pragma unroll
            for (int jj = 0; jj < 4; jj++)
                ldsm_x4(bb[2 * jj][0], bb[2 * jj][1],
                        bb[2 * jj + 1][0], bb[2 * jj + 1][1],
                        Kbase + (uint32_t)(((jj * 16 + b_nrow) * QSW) + b_kw + kw) * 4);
#pragma unroll
            for (int j = 0; j < 8; j++)
                mma_f16(cs[j], a, bb[j]);
        }

        // scale + mask
#pragma unroll
        for (int j = 0; j < 8; j++) {
            int c0 = k0 + j * 8 + 2 * tg;
            int mk0 = msk[c0], mk1 = msk[c0 + 1];
            cs[j][0] = mk0 ? cs[j][0] * scale : -CUDART_INF_F;
            cs[j][1] = mk1 ? cs[j][1] * scale : -CUDART_INF_F;
            cs[j][2] = mk0 ? cs[j][2] * scale : -CUDART_INF_F;
            cs[j][3] = mk1 ? cs[j][3] * scale : -CUDART_INF_F;
        }

        // row max (rows qr+g, qr+g+8); reduce over tg lanes
        float mx0 = -CUDART_INF_F, mx1 = -CUDART_INF_F;
#pragma unroll
        for (int j = 0; j < 8; j++) {
            mx0 = fmaxf(mx0, fmaxf(cs[j][0], cs[j][1]));
            mx1 = fmaxf(mx1, fmaxf(cs[j][2], cs[j][3]));
        }
        mx0 = fmaxf(mx0, __shfl_xor_sync(0xffffffffu, mx0, 1));
        mx0 = fmaxf(mx0, __shfl_xor_sync(0xffffffffu, mx0, 2));
        mx1 = fmaxf(mx1, __shfl_xor_sync(0xffffffffu, mx1, 1));
        mx1 = fmaxf(mx1, __shfl_xor_sync(0xffffffffu, mx1, 2));

        float mn0 = fmaxf(m0, mx0), mn1 = fmaxf(m1, mx1);
        float corr0 = __expf(m0 - mn0), corr1 = __expf(m1 - mn1);
        m0 = mn0; m1 = mn1;

        // P = exp(s-m) -> half(rne), register-resident PV A-fragments
        uint32_t ph0[8], ph1[8];
        float rs0 = 0.f, rs1 = 0.f;
#pragma unroll
        for (int j = 0; j < 8; j++) {
            __half2 h0 = __floats2half2_rn(__expf(cs[j][0] - mn0),
                                           __expf(cs[j][1] - mn0));
            __half2 h1 = __floats2half2_rn(__expf(cs[j][2] - mn1),
                                           __expf(cs[j][3] - mn1));
            ph0[j] = *(uint32_t*)&h0;
            ph1[j] = *(uint32_t*)&h1;
            float2 f0 = __half22float2(h0);
            float2 f1 = __half22float2(h1);
            rs0 += f0.x + f0.y; rs1 += f1.x + f1.y;
        }
        rs0 += __shfl_xor_sync(0xffffffffu, rs0, 1);
        rs0 += __shfl_xor_sync(0xffffffffu, rs0, 2);
        rs1 += __shfl_xor_sync(0xffffffffu, rs1, 1);
        rs1 += __shfl_xor_sync(0xffffffffu, rs1, 2);
        l0 = l0 * corr0 + rs0;
        l1 = l1 * corr1 + rs1;

#pragma unroll
        for (int j = 0; j < 16; j++) {
            co[j][0] *= corr0; co[j][1] *= corr0;
            co[j][2] *= corr1; co[j][3] *= corr1;
        }

        // O += P . V  (B-fragments from row-major V via ldmatrix.trans)
#pragma unroll
        for (int ks2 = 0; ks2 < 4; ks2++) {
            uint32_t a[4] = {ph0[2 * ks2], ph1[2 * ks2],
                             ph0[2 * ks2 + 1], ph1[2 * ks2 + 1]};
            uint32_t bb[16][2];
#pragma unroll
            for (int jj = 0; jj < 8; jj++)
                ldsm_x4_t(bb[2 * jj][0], bb[2 * jj][1],
                          bb[2 * jj + 1][0], bb[2 * jj + 1][1],
                          Vbase + (uint32_t)(((ks2 * 16 + v_row) * QSW) + jj * 8 + v_cw) * 4);
#pragma unroll
            for (int j2 = 0; j2 < 16; j2++)
                mma_f16(co[j2], a, bb[j2]);
        }

        __syncthreads();   // buffer kt&1 fully read before iter kt+1 overwrites it
    }

    // Epilogue: normalize, store half
    float inv0 = 1.f / l0, inv1 = 1.f / l1;
    size_t r0 = (size_t)(q0 + qr + g);
    size_t r1 = r0 + 8;
#pragma unroll
    for (int j2 = 0; j2 < 16; j2++) {
        int col = j2 * 8 + 2 * tg;
        __half2 h0 = __floats2half2_rn(co[j2][0] * inv0, co[j2][1] * inv0);
        __half2 h1 = __floats2half2_rn(co[j2][2] * inv1, co[j2][3] * inv1);
        *(__half2*)&O[base + r0 * DM + col] = h0;
        *(__half2*)&O[base + r1 * DM + col] = h1;
    }
}

// ---------------------------------------------------------------------------
extern "C" void kernel_launch(void* const* d_in, const int* in_sizes, int n_in,
                              void* d_out, int out_size)
{
    const float* x  = (const float*)d_in[0];
    const int* mask = (const int*)d_in[1];
    const float* Wq = (const float*)d_in[2];
    const float* bq = (const float*)d_in[3];
    const float* Wk = (const float*)d_in[4];
    const float* bk = (const float*)d_in[5];
    const float* Wv = (const float*)d_in[6];
    const float* bv = (const float*)d_in[7];
    const float* Wo = (const float*)d_in[8];
    const float* bo = (const float*)d_in[9];
    float* out = (float*)d_out;

    __half *xh, *wh, *qh, *kh, *vh, *ah;
    float* bias3;
    cudaGetSymbolAddress((void**)&xh, g_xh);
    cudaGetSymbolAddress((void**)&wh, g_wh);
    cudaGetSymbolAddress((void**)&qh, g_qh);
    cudaGetSymbolAddress((void**)&kh, g_kh);
    cudaGetSymbolAddress((void**)&vh, g_vh);
    cudaGetSymbolAddress((void**)&ah, g_ah);
    cudaGetSymbolAddress((void**)&bias3, g_bias3);

    cudaFuncSetAttribute(gemm_f16_kernel,
                         cudaFuncAttributeMaxDynamicSharedMemorySize, GEMM_SMEM);
    cudaFuncSetAttribute(flash_f16_kernel,
                         cudaFuncAttributeMaxDynamicSharedMemorySize,
                         FLASH_SMEM_BYTES);

    const int NX4 = MR * DM / 4;
    const int NW4 = DM * DM / 4;

    // fp32 -> fp16 conversion (rne); bias concat
    cvt_f2h_kernel<<<2048, 256>>>(x,  xh, NX4);
    cvt_f2h_kernel<<<1024, 256>>>(Wq, wh + 0 * (size_t)DM * DM, NW4);
    cvt_f2h_kernel<<<1024, 256>>>(Wk, wh + 1 * (size_t)DM * DM, NW4);
    cvt_f2h_kernel<<<1024, 256>>>(Wv, wh + 2 * (size_t)DM * DM, NW4);
    cvt_f2h_kernel<<<1024, 256>>>(Wo, wh + 3 * (size_t)DM * DM, NW4);
    pack_bias_kernel<<<8, 256>>>(bq, bk, bv, bias3);

    // Fused QKV projection: N = 6144 over concatenated weights
    dim3 qkvgrid(NQKV / BN, MR / BM);  // (48, 64)
    gemm_f16_kernel<<<qkvgrid, GTHREADS, GEMM_SMEM>>>(
        xh, wh, bias3, qh, kh, vh, 1);

    flash_f16_kernel<<<dim3(NB * NHEADS, TS / FQ), 256, FLASH_SMEM_BYTES>>>(
        qh, kh, vh, mask, ah);

    // Final projection (float output)
    dim3 ogrid(DM / BN, MR / BM);      // (16, 64)
    gemm_f16_kernel<<<ogrid, GTHREADS, GEMM_SMEM>>>(
        ah, wh + 3 * (size_t)DM * DM, bo, out, nullptr, nullptr, 0);
}

// round 15
// speedup vs baseline: 1.4936x; 1.0056x over previous
#include <cuda_runtime.h>
#include <cuda_fp16.h>
#include <math_constants.h>
#include <cstdint>

#define DM 2048
#define TS 2048
#define NB 4
#define NHEADS 16
#define HD 128
#define MR (NB * TS)   // 8192 rows
#define NQKV (3 * DM)  // 6144

// Scratch (device-global: no allocations allowed in kernel_launch)
__device__ __half g_xh[MR * DM];
__device__ __half g_wh[4 * DM * DM];
__device__ __half g_qh[MR * DM];
__device__ __half g_kh[MR * DM];
__device__ __half g_vh[MR * DM];
__device__ __half g_ah[MR * DM];
__device__ float  g_bias3[NQKV];

// ===========================================================================
// helpers
// ===========================================================================
__device__ __forceinline__ uint32_t smem_u32(const void* p) {
    uint32_t a;
    asm("{ .reg .u64 t; cvta.to.shared.u64 t, %1; cvt.u32.u64 %0, t; }"
        : "=r"(a) : "l"(p));
    return a;
}

__device__ __forceinline__ void cpasync16(uint32_t s, const void* g) {
    asm volatile("cp.async.cg.shared.global [%0], [%1], 16;" :: "r"(s), "l"(g));
}
#define CP_COMMIT() asm volatile("cp.async.commit_group;" ::: "memory")
#define CP_WAIT(n)  asm volatile("cp.async.wait_group %0;" :: "n"(n) : "memory")

__device__ __forceinline__ void mma_f16(float* c, const uint32_t* a,
                                        const uint32_t* b) {
    asm volatile(
        "mma.sync.aligned.m16n8k16.row.col.f32.f16.f16.f32 "
        "{%0,%1,%2,%3}, {%4,%5,%6,%7}, {%8,%9}, {%0,%1,%2,%3};"
        : "+f"(c[0]), "+f"(c[1]), "+f"(c[2]), "+f"(c[3])
        : "r"(a[0]), "r"(a[1]), "r"(a[2]), "r"(a[3]), "r"(b[0]), "r"(b[1]));
}

__device__ __forceinline__ void ldsm_x4(uint32_t& r0, uint32_t& r1,
                                        uint32_t& r2, uint32_t& r3,
                                        uint32_t addr) {
    asm volatile(
        "ldmatrix.sync.aligned.m8n8.x4.shared.b16 {%0,%1,%2,%3}, [%4];"
        : "=r"(r0), "=r"(r1), "=r"(r2), "=r"(r3) : "r"(addr));
}

__device__ __forceinline__ void ldsm_x4_t(uint32_t& r0, uint32_t& r1,
                                          uint32_t& r2, uint32_t& r3,
                                          uint32_t addr) {
    asm volatile(
        "ldmatrix.sync.aligned.m8n8.x4.trans.shared.b16 {%0,%1,%2,%3}, [%4];"
        : "=r"(r0), "=r"(r1), "=r"(r2), "=r"(r3) : "r"(addr));
}

// ===========================================================================
// fp32 -> fp16 conversion (rne): x separate, 4 weights merged; bias concat
// ===========================================================================
__global__ void cvt_f2h_kernel(const float* __restrict__ in,
                               __half* __restrict__ out, int n4) {
    int i = blockIdx.x * blockDim.x + threadIdx.x;
    int stride = gridDim.x * blockDim.x;
    for (; i < n4; i += stride) {
        float4 v = ((const float4*)in)[i];
        __half2 h0 = __floats2half2_rn(v.x, v.y);
        __half2 h1 = __floats2half2_rn(v.z, v.w);
        uint2 o = {*(uint32_t*)&h0, *(uint32_t*)&h1};
        ((uint2*)out)[i] = o;
    }
}

__global__ void cvt4_f2h_kernel(const float* __restrict__ s0,
                                const float* __restrict__ s1,
                                const float* __restrict__ s2,
                                const float* __restrict__ s3,
                                __half* __restrict__ out, int seg4) {
    int i = blockIdx.x * blockDim.x + threadIdx.x;
    int stride = gridDim.x * blockDim.x;
    int total = 4 * seg4;
    for (; i < total; i += stride) {
        int which = i / seg4;
        int off = i - which * seg4;
        const float* src = (which == 0) ? s0 : (which == 1) ? s1
                         : (which == 2) ? s2 : s3;
        float4 v = ((const float4*)src)[off];
        __half2 h0 = __floats2half2_rn(v.x, v.y);
        __half2 h1 = __floats2half2_rn(v.z, v.w);
        uint2 o = {*(uint32_t*)&h0, *(uint32_t*)&h1};
        ((uint2*)out)[i] = o;
    }
}

__global__ void pack_bias_kernel(const float* __restrict__ a,
                                 const float* __restrict__ b,
                                 const float* __restrict__ c,
                                 float* __restrict__ o) {
    int i = blockIdx.x * blockDim.x + threadIdx.x;
    if (i < DM) {
        o[i] = a[i];
        o[i + DM] = b[i];
        o[i + 2 * DM] = c[i];
    }
}

// ===========================================================================
// fp16 mma.sync GEMM (ldmatrix fragments, 2 CTAs/SM, single-barrier pipe).
// Block tile 128x128, K-chunk 64 halves, 3-slot cp.async ring (108 KB smem),
// 256 threads, warp tile 64x32. Loads issued AFTER the barrier so the
// trailing barrier is unnecessary (1 sync per chunk).
// Fused QKV epilogue by (bn >> 11).
// ===========================================================================
#define BM 128
#define BN 128
#define BKH 64
#define RSW 36                                  // row stride in 4B words
#define STAGE_WORDS ((BM + BN) * RSW)           // 9216
#define GEMM_SMEM (3 * STAGE_WORDS * 4)         // 110592
#define GTHREADS 256

__device__ __forceinline__ void load_chunk_h(const __half* __restrict__ A,
                                             const __half* __restrict__ W,
                                             uint32_t base, int slot,
                                             int bm, int bn, int k0, int tid) {
    uint32_t sa = base + slot * STAGE_WORDS * 4;
#pragma unroll
    for (int r = 0; r < 4; r++) {          // A: 128 rows x 8 x 16B
        int idx = r * GTHREADS + tid;
        int row = idx >> 3, q = idx & 7;
        cpasync16(sa + (row * RSW + q * 4) * 4,
                  A + (size_t)(bm + row) * DM + k0 + q * 8);
    }
    uint32_t sb = sa + BM * RSW * 4;
#pragma unroll
    for (int r = 0; r < 4; r++) {          // B: 128 rows x 8 x 16B
        int idx = r * GTHREADS + tid;
        int row = idx >> 3, q = idx & 7;
        cpasync16(sb + (row * RSW + q * 4) * 4,
                  W + (size_t)(bn + row) * DM + k0 + q * 8);
    }
    CP_COMMIT();
}

__global__ __launch_bounds__(GTHREADS, 2)
void gemm_f16_kernel(const __half* __restrict__ A,
                     const __half* __restrict__ W,
                     const float* __restrict__ bias,
                     void* __restrict__ C0,
                     void* __restrict__ C1,
                     void* __restrict__ C2,
                     int outHalf)
{
    extern __shared__ uint32_t smw[];

    const int tid = threadIdx.x;
    const int bm = blockIdx.y * BM;
    const int bn = blockIdx.x * BN;
    const int wid = tid >> 5;
    const int lane = tid & 31;
    const int wm = wid & 1;
    const int wn = wid >> 1;
    const int g = lane >> 2;
    const int tg = lane & 3;
    uint32_t base = smem_u32(smw);

    const int a_row = wm * 64 + ((lane >> 3) & 1) * 8 + (lane & 7);
    const int a_kw  = ((lane >> 4) & 1) * 4;
    const int b_row = wn * 32 + ((lane >> 4) & 1) * 8 + (lane & 7);
    const int b_kw  = ((lane >> 3) & 1) * 4;

    float c[4][4][4];
#pragma unroll
    for (int i = 0; i < 4; i++)
#pragma unroll
        for (int j = 0; j < 4; j++)
#pragma unroll
            for (int v = 0; v < 4; v++) c[i][j][v] = 0.f;

    // Prologue: 2 chunks in flight
    load_chunk_h(A, W, base, 0, bm, bn, 0 * BKH, tid);
    load_chunk_h(A, W, base, 1, bm, bn, 1 * BKH, tid);

    const int NCHUNK = DM / BKH;    // 32
    for (int k = 0; k < NCHUNK; k++) {
        if (k + 1 < NCHUNK) { CP_WAIT(1); } else { CP_WAIT(0); }
        __syncthreads();      // chunk k ready; all warps done with slot (k+2)%3
        if (k + 2 < NCHUNK)
            load_chunk_h(A, W, base, (k + 2) % 3, bm, bn, (k + 2) * BKH, tid);

        int slot = k % 3;
        uint32_t Abase = base + slot * STAGE_WORDS * 4;
        uint32_t Bbase = Abase + BM * RSW * 4;

#pragma unroll
        for (int kw = 0; kw < 32; kw += 8) {
            uint32_t a[4][4], b[4][2];
#pragma unroll
            for (int i = 0; i < 4; i++)
                ldsm_x4(a[i][0], a[i][1], a[i][2], a[i][3],
                        Abase + (uint32_t)(((a_row + i * 16) * RSW) + a_kw + kw) * 4);
#pragma unroll
            for (int jj = 0; jj < 2; jj++)
                ldsm_x4(b[2 * jj][0], b[2 * jj][1], b[2 * jj + 1][0], b[2 * jj + 1][1],
                        Bbase + (uint32_t)(((b_row + jj * 16) * RSW) + b_kw + kw) * 4);
#pragma unroll
            for (int i = 0; i < 4; i++)
#pragma unroll
                for (int j = 0; j < 4; j++)
                    mma_f16(c[i][j], a[i], b[j]);
        }
    }

    const int which = bn >> 11;
    void* Csel = (which == 0) ? C0 : ((which == 1) ? C1 : C2);

#pragma unroll
    for (int j = 0; j < 4; j++) {
        int col = bn + wn * 32 + j * 8 + 2 * tg;
        int coll = col & (DM - 1);
        float b0 = bias[col], b1 = bias[col + 1];
#pragma unroll
        for (int i = 0; i < 4; i++) {
            int row0 = bm + wm * 64 + i * 16 + g;
            float v00 = c[i][j][0] + b0, v01 = c[i][j][1] + b1;
            float v10 = c[i][j][2] + b0, v11 = c[i][j][3] + b1;
            if (outHalf) {
                __half* C = (__half*)Csel;
                __half2 h0 = __floats2half2_rn(v00, v01);
                __half2 h1 = __floats2half2_rn(v10, v11);
                *(__half2*)&C[(size_t)row0 * DM + coll] = h0;
                *(__half2*)&C[(size_t)(row0 + 8) * DM + coll] = h1;
            } else {
                float* C = (float*)Csel;
                *(float2*)&C[(size_t)row0 * DM + coll] = make_float2(v00, v01);
                *(float2*)&C[(size_t)(row0 + 8) * DM + coll] = make_float2(v10, v11);
            }
        }
    }
}

// ===========================================================================
// Tensor-core flash attention (fp16 mma.sync, fp32 softmax/accum).
// 3-buffer cp.async K/V ring, loads issued post-barrier (1 sync per tile).
// V row-major + ldmatrix.trans; P register-resident; mask cached once.
// ===========================================================================
#define FQ 128
#define FK 64
#define QSW 68                       // Q/K/V row stride in words (136 halves)
#define TILE_WORDS (FK * QSW)        // 4352

#define OFF_Q   0
#define OFF_KV  (FQ * QSW)                       // 8704
#define OFF_MSK (OFF_KV + 6 * TILE_WORDS)        // 34816
#define FLASH_SMEM_BYTES ((OFF_MSK + TS) * 4)    // 147456

__device__ __forceinline__ void flash_load_kv(const __half* __restrict__ K,
                                              const __half* __restrict__ V,
                                              uint32_t kvbase, int buf,
                                              size_t base, int k0, int tid) {
    uint32_t kb = kvbase + buf * 2 * TILE_WORDS * 4;
    uint32_t vb = kb + TILE_WORDS * 4;
#pragma unroll
    for (int r = 0; r < 4; r++) {        // K: 64 rows x 16 x 16B
        int idx = r * 256 + tid;
        int row = idx >> 4, q = idx & 15;
        cpasync16(kb + (row * QSW + q * 4) * 4,
                  K + base + (size_t)(k0 + row) * DM + q * 8);
    }
#pragma unroll
    for (int r = 0; r < 4; r++) {        // V: 64 rows x 16 x 16B
        int idx = r * 256 + tid;
        int row = idx >> 4, q = idx & 15;
        cpasync16(vb + (row * QSW + q * 4) * 4,
                  V + base + (size_t)(k0 + row) * DM + q * 8);
    }
    CP_COMMIT();
}

__global__ __launch_bounds__(256, 1)
void flash_f16_kernel(const __half* __restrict__ Q, const __half* __restrict__ K,
                      const __half* __restrict__ V, const int* __restrict__ mask,
                      __half* __restrict__ O)
{
    extern __shared__ uint32_t smw[];
    uint32_t* Qs = smw + OFF_Q;
    int*      msk = (int*)(smw + OFF_MSK);

    const int tid = threadIdx.x;
    const int wid = tid >> 5;
    const int lane = tid & 31;
    const int g = lane >> 2;
    const int tg = lane & 3;
    const int b = blockIdx.x >> 4;
    const int h = blockIdx.x & 15;
    const int q0 = blockIdx.y * FQ;
    const size_t base = (size_t)b * TS * DM + (size_t)h * HD;
    const float scale = 0.08838834764831845f;
    const int qr = wid * 16;

    const int a_mrow = ((lane >> 3) & 1) * 8 + (lane & 7);   // Q (non-trans)
    const int a_kw   = ((lane >> 4) & 1) * 4;
    const int b_nrow = ((lane >> 4) & 1) * 8 + (lane & 7);   // K (non-trans)
    const int b_kw   = ((lane >> 3) & 1) * 4;
    const int v_row  = ((lane >> 3) & 1) * 8 + (lane & 7);   // V (trans): key row
    const int v_cw   = ((lane >> 4) & 1) * 4;                // V: d col words

    const uint32_t Qbase  = smem_u32(Qs);
    const uint32_t KVbase = smem_u32(smw + OFF_KV);

    // Prologue: Q + K/V tile 0 (one group), then tile 1 (second group)
#pragma unroll
    for (int r = 0; r < 8; r++) {
        int idx = r * 256 + tid;
        int row = idx >> 4, q = idx & 15;
        cpasync16(Qbase + (uint32_t)(row * QSW + q * 4) * 4,
                  Q + base + (size_t)(q0 + row) * DM + q * 8);
    }
    flash_load_kv(K, V, KVbase, 0, base, 0, tid);      // commits Q + tile0
    flash_load_kv(K, V, KVbase, 1, base, FK, tid);     // tile1
    for (int i = tid; i < TS; i += 256) msk[i] = mask[b * TS + i];

    float m0 = -CUDART_INF_F, m1 = -CUDART_INF_F;
    float l0 = 0.f, l1 = 0.f;
    float co[16][4];
#pragma unroll
    for (int j = 0; j < 16; j++)
#pragma unroll
        for (int v = 0; v < 4; v++) co[j][v] = 0.f;

    const int NT = TS / FK;   // 32
    for (int kt = 0; kt < NT; kt++) {
        const int k0 = kt * FK;
        if (kt + 1 < NT) { CP_WAIT(1); } else { CP_WAIT(0); }
        __syncthreads();     // tile kt ready; all warps done with buf (kt+2)%3
        if (kt + 2 < NT)
            flash_load_kv(K, V, KVbase, (kt + 2) % 3, base, k0 + 2 * FK, tid);

        const uint32_t Kbase = KVbase + (uint32_t)((kt % 3) * 2 * TILE_WORDS) * 4;
        const uint32_t Vbase = Kbase + (uint32_t)TILE_WORDS * 4;

        // S = Q . K^T
        float cs[8][4];
#pragma unroll
        for (int j = 0; j < 8; j++)
#pragma unroll
            for (int v = 0; v < 4; v++) cs[j][v] = 0.f;

#pragma unroll
        for (int ks = 0; ks < 8; ks++) {
            int kw = ks * 8;
            uint32_t a[4], bb[8][2];
            ldsm_x4(a[0], a[1], a[2], a[3],
                    Qbase + (uint32_t)(((qr + a_mrow) * QSW) + a_kw + kw) * 4);
#pragma unroll
            for (int jj = 0; jj < 4; jj++)
                ldsm_x4(bb[2 * jj][0], bb[2 * jj][1],
                        bb[2 * jj + 1][0], bb[2 * jj + 1][1],
                        Kbase + (uint32_t)(((jj * 16 + b_nrow) * QSW) + b_kw + kw) * 4);
#pragma unroll
            for (int j = 0; j < 8; j++)
                mma_f16(cs[j], a, bb[j]);
        }

        // scale + mask
#pragma unroll
        for (int j = 0; j < 8; j++) {
            int c0 = k0 + j * 8 + 2 * tg;
            int mk0 = msk[c0], mk1 = msk[c0 + 1];
            cs[j][0] = mk0 ? cs[j][0] * scale : -CUDART_INF_F;
            cs[j][1] = mk1 ? cs[j][1] * scale : -CUDART_INF_F;
            cs[j][2] = mk0 ? cs[j][2] * scale : -CUDART_INF_F;
            cs[j][3] = mk1 ? cs[j][3] * scale : -CUDART_INF_F;
        }

        // row max (rows qr+g, qr+g+8); reduce over tg lanes
        float mx0 = -CUDART_INF_F, mx1 = -CUDART_INF_F;
#pragma unroll
        for (int j = 0; j < 8; j++) {
            mx0 = fmaxf(mx0, fmaxf(cs[j][0], cs[j][1]));
            mx1 = fmaxf(mx1, fmaxf(cs[j][2], cs[j][3]));
        }
        mx0 = fmaxf(mx0, __shfl_xor_sync(0xffffffffu, mx0, 1));
        mx0 = fmaxf(mx0, __shfl_xor_sync(0xffffffffu, mx0, 2));
        mx1 = fmaxf(mx1, __shfl_xor_sync(0xffffffffu, mx1, 1));
        mx1 = fmaxf(mx1, __shfl_xor_sync(0xffffffffu, mx1, 2));

        float mn0 = fmaxf(m0, mx0), mn1 = fmaxf(m1, mx1);
        float corr0 = __expf(m0 - mn0), corr1 = __expf(m1 - mn1);
        m0 = mn0; m1 = mn1;

        // P = exp(s-m) -> half(rne), register-resident PV A-fragments
        uint32_t ph0[8], ph1[8];
        float rs0 = 0.f, rs1 = 0.f;
#pragma unroll
        for (int j = 0; j < 8; j++) {
            __half2 h0 = __floats2half2_rn(__expf(cs[j][0] - mn0),
                                           __expf(cs[j][1] - mn0));
            __half2 h1 = __floats2half2_rn(__expf(cs[j][2] - mn1),
                                           __expf(cs[j][3] - mn1));
            ph0[j] = *(uint32_t*)&h0;
            ph1[j] = *(uint32_t*)&h1;
            float2 f0 = __half22float2(h0);
            float2 f1 = __half22float2(h1);
            rs0 += f0.x + f0.y; rs1 += f1.x + f1.y;
        }
        rs0 += __shfl_xor_sync(0xffffffffu, rs0, 1);
        rs0 += __shfl_xor_sync(0xffffffffu, rs0, 2);
        rs1 += __shfl_xor_sync(0xffffffffu, rs1, 1);
        rs1 += __shfl_xor_sync(0xffffffffu, rs1, 2);
        l0 = l0 * corr0 + rs0;
        l1 = l1 * corr1 + rs1;

#pragma unroll
        for (int j = 0; j < 16; j++) {
            co[j][0] *= corr0; co[j][1] *= corr0;
            co[j][2] *= corr1; co[j][3] *= corr1;
        }

        // O += P . V  (B-fragments from row-major V via ldmatrix.trans)
#pragma unroll
        for (int ks2 = 0; ks2 < 4; ks2++) {
            uint32_t a[4] = {ph0[2 * ks2], ph1[2 * ks2],
                             ph0[2 * ks2 + 1], ph1[2 * ks2 + 1]};
            uint32_t bb[16][2];
#pragma unroll
            for (int jj = 0; jj < 8; jj++)
                ldsm_x4_t(bb[2 * jj][0], bb[2 * jj][1],
                          bb[2 * jj + 1][0], bb[2 * jj + 1][1],
                          Vbase + (uint32_t)(((ks2 * 16 + v_row) * QSW) + jj * 8 + v_cw) * 4);
#pragma unroll
            for (int j2 = 0; j2 < 16; j2++)
                mma_f16(co[j2], a, bb[j2]);
        }
    }

    // Epilogue: normalize, store half
    float inv0 = 1.f / l0, inv1 = 1.f / l1;
    size_t r0 = (size_t)(q0 + qr + g);
    size_t r1 = r0 + 8;
#pragma unroll
    for (int j2 = 0; j2 < 16; j2++) {
        int col = j2 * 8 + 2 * tg;
        __half2 h0 = __floats2half2_rn(co[j2][0] * inv0, co[j2][1] * inv0);
        __half2 h1 = __floats2half2_rn(co[j2][2] * inv1, co[j2][3] * inv1);
        *(__half2*)&O[base + r0 * DM + col] = h0;
        *(__half2*)&O[base + r1 * DM + col] = h1;
    }
}

// ---------------------------------------------------------------------------
extern "C" void kernel_launch(void* const* d_in, const int* in_sizes, int n_in,
                              void* d_out, int out_size)
{
    const float* x  = (const float*)d_in[0];
    const int* mask = (const int*)d_in[1];
    const float* Wq = (const float*)d_in[2];
    const float* bq = (const float*)d_in[3];
    const float* Wk = (const float*)d_in[4];
    const float* bk = (const float*)d_in[5];
    const float* Wv = (const float*)d_in[6];
    const float* bv = (const float*)d_in[7];
    const float* Wo = (const float*)d_in[8];
    const float* bo = (const float*)d_in[9];
    float* out = (float*)d_out;

    __half *xh, *wh, *qh, *kh, *vh, *ah;
    float* bias3;
    cudaGetSymbolAddress((void**)&xh, g_xh);
    cudaGetSymbolAddress((void**)&wh, g_wh);
    cudaGetSymbolAddress((void**)&qh, g_qh);
    cudaGetSymbolAddress((void**)&kh, g_kh);
    cudaGetSymbolAddress((void**)&vh, g_vh);
    cudaGetSymbolAddress((void**)&ah, g_ah);
    cudaGetSymbolAddress((void**)&bias3, g_bias3);

    cudaFuncSetAttribute(gemm_f16_kernel,
                         cudaFuncAttributeMaxDynamicSharedMemorySize, GEMM_SMEM);
    cudaFuncSetAttribute(flash_f16_kernel,
                         cudaFuncAttributeMaxDynamicSharedMemorySize,
                         FLASH_SMEM_BYTES);

    const int NX4 = MR * DM / 4;
    const int NW4 = DM * DM / 4;

    // fp32 -> fp16 conversion (rne): x separate, 4 weights merged; bias concat
    cvt_f2h_kernel<<<2048, 256>>>(x, xh, NX4);
    cvt4_f2h_kernel<<<4096, 256>>>(Wq, Wk, Wv, Wo, wh, NW4);
    pack_bias_kernel<<<8, 256>>>(bq, bk, bv, bias3);

    // Fused QKV projection: N = 6144 over concatenated weights
    dim3 qkvgrid(NQKV / BN, MR / BM);  // (48, 64)
    gemm_f16_kernel<<<qkvgrid, GTHREADS, GEMM_SMEM>>>(
        xh, wh, bias3, qh, kh, vh, 1);

    flash_f16_kernel<<<dim3(NB * NHEADS, TS / FQ), 256, FLASH_SMEM_BYTES>>>(
        qh, kh, vh, mask, ah);

    // Final projection (float output)
    dim3 ogrid(DM / BN, MR / BM);      // (16, 64)
    gemm_f16_kernel<<<ogrid, GTHREADS, GEMM_SMEM>>>(
        ah, wh + 3 * (size_t)DM * DM, bo, out, nullptr, nullptr, 0);
}

// round 16
// speedup vs baseline: 1.5618x; 1.0456x over previous
#include <cuda_runtime.h>
#include <cuda_fp16.h>
#include <math_constants.h>
#include <cstdint>

#define DM 2048
#define TS 2048
#define NB 4
#define NHEADS 16
#define HD 128
#define MR (NB * TS)   // 8192 rows
#define NQKV (3 * DM)  // 6144

// Scratch (device-global: no allocations allowed in kernel_launch)
__device__ __half g_xh[MR * DM];
__device__ __half g_wh[4 * DM * DM];
__device__ __half g_qh[MR * DM];
__device__ __half g_kh[MR * DM];
__device__ __half g_vh[MR * DM];
__device__ __half g_ah[MR * DM];
__device__ float  g_bias3[NQKV];

// ===========================================================================
// helpers
// ===========================================================================
__device__ __forceinline__ uint32_t smem_u32(const void* p) {
    uint32_t a;
    asm("{ .reg .u64 t; cvta.to.shared.u64 t, %1; cvt.u32.u64 %0, t; }"
        : "=r"(a) : "l"(p));
    return a;
}

__device__ __forceinline__ void cpasync16(uint32_t s, const void* g) {
    asm volatile("cp.async.cg.shared.global [%0], [%1], 16;" :: "r"(s), "l"(g));
}
#define CP_COMMIT() asm volatile("cp.async.commit_group;" ::: "memory")
#define CP_WAIT(n)  asm volatile("cp.async.wait_group %0;" :: "n"(n) : "memory")

__device__ __forceinline__ void mma_f16(float* c, const uint32_t* a,
                                        const uint32_t* b) {
    asm volatile(
        "mma.sync.aligned.m16n8k16.row.col.f32.f16.f16.f32 "
        "{%0,%1,%2,%3}, {%4,%5,%6,%7}, {%8,%9}, {%0,%1,%2,%3};"
        : "+f"(c[0]), "+f"(c[1]), "+f"(c[2]), "+f"(c[3])
        : "r"(a[0]), "r"(a[1]), "r"(a[2]), "r"(a[3]), "r"(b[0]), "r"(b[1]));
}

__device__ __forceinline__ void ldsm_x4(uint32_t& r0, uint32_t& r1,
                                        uint32_t& r2, uint32_t& r3,
                                        uint32_t addr) {
    asm volatile(
        "ldmatrix.sync.aligned.m8n8.x4.shared.b16 {%0,%1,%2,%3}, [%4];"
        : "=r"(r0), "=r"(r1), "=r"(r2), "=r"(r3) : "r"(addr));
}

__device__ __forceinline__ void ldsm_x4_t(uint32_t& r0, uint32_t& r1,
                                          uint32_t& r2, uint32_t& r3,
                                          uint32_t addr) {
    asm volatile(
        "ldmatrix.sync.aligned.m8n8.x4.trans.shared.b16 {%0,%1,%2,%3}, [%4];"
        : "=r"(r0), "=r"(r1), "=r"(r2), "=r"(r3) : "r"(addr));
}

// ===========================================================================
// fp32 -> fp16 conversion (rne): x + 4 weights in ONE kernel; bias concat
// ===========================================================================
__global__ void cvt_all_kernel(const float* __restrict__ x,
                               const float* __restrict__ w0,
                               const float* __restrict__ w1,
                               const float* __restrict__ w2,
                               const float* __restrict__ w3,
                               __half* __restrict__ xh,
                               __half* __restrict__ wh,
                               int nx4, int nw4) {
    int i = blockIdx.x * blockDim.x + threadIdx.x;
    int stride = gridDim.x * blockDim.x;
    int total = nx4 + 4 * nw4;
    for (; i < total; i += stride) {
        const float* src;
        __half* dst;
        int off;
        if (i < nx4) {
            src = x; dst = xh; off = i;
        } else {
            int j = i - nx4;
            int which = j / nw4;
            off = j - which * nw4;
            src = (which == 0) ? w0 : (which == 1) ? w1
                : (which == 2) ? w2 : w3;
            dst = wh + (size_t)which * DM * DM;
        }
        float4 v = ((const float4*)src)[off];
        __half2 h0 = __floats2half2_rn(v.x, v.y);
        __half2 h1 = __floats2half2_rn(v.z, v.w);
        uint2 o = {*(uint32_t*)&h0, *(uint32_t*)&h1};
        ((uint2*)dst)[off] = o;
    }
}

__global__ void pack_bias_kernel(const float* __restrict__ a,
                                 const float* __restrict__ b,
                                 const float* __restrict__ c,
                                 float* __restrict__ o) {
    int i = blockIdx.x * blockDim.x + threadIdx.x;
    if (i < DM) {
        o[i] = a[i];
        o[i + DM] = b[i];
        o[i + 2 * DM] = c[i];
    }
}

// ===========================================================================
// fp16 mma.sync GEMM (unchanged R15 winner: ldmatrix fragments, 2 CTAs/SM,
// single-barrier 3-slot cp.async ring). Fused QKV epilogue by (bn >> 11).
// ===========================================================================
#define BM 128
#define BN 128
#define BKH 64
#define RSW 36                                  // row stride in 4B words
#define STAGE_WORDS ((BM + BN) * RSW)           // 9216
#define GEMM_SMEM (3 * STAGE_WORDS * 4)         // 110592
#define GTHREADS 256

__device__ __forceinline__ void load_chunk_h(const __half* __restrict__ A,
                                             const __half* __restrict__ W,
                                             uint32_t base, int slot,
                                             int bm, int bn, int k0, int tid) {
    uint32_t sa = base + slot * STAGE_WORDS * 4;
#pragma unroll
    for (int r = 0; r < 4; r++) {          // A: 128 rows x 8 x 16B
        int idx = r * GTHREADS + tid;
        int row = idx >> 3, q = idx & 7;
        cpasync16(sa + (row * RSW + q * 4) * 4,
                  A + (size_t)(bm + row) * DM + k0 + q * 8);
    }
    uint32_t sb = sa + BM * RSW * 4;
#pragma unroll
    for (int r = 0; r < 4; r++) {          // B: 128 rows x 8 x 16B
        int idx = r * GTHREADS + tid;
        int row = idx >> 3, q = idx & 7;
        cpasync16(sb + (row * RSW + q * 4) * 4,
                  W + (size_t)(bn + row) * DM + k0 + q * 8);
    }
    CP_COMMIT();
}

__global__ __launch_bounds__(GTHREADS, 2)
void gemm_f16_kernel(const __half* __restrict__ A,
                     const __half* __restrict__ W,
                     const float* __restrict__ bias,
                     void* __restrict__ C0,
                     void* __restrict__ C1,
                     void* __restrict__ C2,
                     int outHalf)
{
    extern __shared__ uint32_t smw[];

    const int tid = threadIdx.x;
    const int bm = blockIdx.y * BM;
    const int bn = blockIdx.x * BN;
    const int wid = tid >> 5;
    const int lane = tid & 31;
    const int wm = wid & 1;
    const int wn = wid >> 1;
    const int g = lane >> 2;
    const int tg = lane & 3;
    uint32_t base = smem_u32(smw);

    const int a_row = wm * 64 + ((lane >> 3) & 1) * 8 + (lane & 7);
    const int a_kw  = ((lane >> 4) & 1) * 4;
    const int b_row = wn * 32 + ((lane >> 4) & 1) * 8 + (lane & 7);
    const int b_kw  = ((lane >> 3) & 1) * 4;

    float c[4][4][4];
#pragma unroll
    for (int i = 0; i < 4; i++)
#pragma unroll
        for (int j = 0; j < 4; j++)
#pragma unroll
            for (int v = 0; v < 4; v++) c[i][j][v] = 0.f;

    load_chunk_h(A, W, base, 0, bm, bn, 0 * BKH, tid);
    load_chunk_h(A, W, base, 1, bm, bn, 1 * BKH, tid);

    const int NCHUNK = DM / BKH;    // 32
    for (int k = 0; k < NCHUNK; k++) {
        if (k + 1 < NCHUNK) { CP_WAIT(1); } else { CP_WAIT(0); }
        __syncthreads();
        if (k + 2 < NCHUNK)
            load_chunk_h(A, W, base, (k + 2) % 3, bm, bn, (k + 2) * BKH, tid);

        int slot = k % 3;
        uint32_t Abase = base + slot * STAGE_WORDS * 4;
        uint32_t Bbase = Abase + BM * RSW * 4;

#pragma unroll
        for (int kw = 0; kw < 32; kw += 8) {
            uint32_t a[4][4], b[4][2];
#pragma unroll
            for (int i = 0; i < 4; i++)
                ldsm_x4(a[i][0], a[i][1], a[i][2], a[i][3],
                        Abase + (uint32_t)(((a_row + i * 16) * RSW) + a_kw + kw) * 4);
#pragma unroll
            for (int jj = 0; jj < 2; jj++)
                ldsm_x4(b[2 * jj][0], b[2 * jj][1], b[2 * jj + 1][0], b[2 * jj + 1][1],
                        Bbase + (uint32_t)(((b_row + jj * 16) * RSW) + b_kw + kw) * 4);
#pragma unroll
            for (int i = 0; i < 4; i++)
#pragma unroll
                for (int j = 0; j < 4; j++)
                    mma_f16(c[i][j], a[i], b[j]);
        }
    }

    const int which = bn >> 11;
    void* Csel = (which == 0) ? C0 : ((which == 1) ? C1 : C2);

#pragma unroll
    for (int j = 0; j < 4; j++) {
        int col = bn + wn * 32 + j * 8 + 2 * tg;
        int coll = col & (DM - 1);
        float b0 = bias[col], b1 = bias[col + 1];
#pragma unroll
        for (int i = 0; i < 4; i++) {
            int row0 = bm + wm * 64 + i * 16 + g;
            float v00 = c[i][j][0] + b0, v01 = c[i][j][1] + b1;
            float v10 = c[i][j][2] + b0, v11 = c[i][j][3] + b1;
            if (outHalf) {
                __half* C = (__half*)Csel;
                __half2 h0 = __floats2half2_rn(v00, v01);
                __half2 h1 = __floats2half2_rn(v10, v11);
                *(__half2*)&C[(size_t)row0 * DM + coll] = h0;
                *(__half2*)&C[(size_t)(row0 + 8) * DM + coll] = h1;
            } else {
                float* C = (float*)Csel;
                *(float2*)&C[(size_t)row0 * DM + coll] = make_float2(v00, v01);
                *(float2*)&C[(size_t)(row0 + 8) * DM + coll] = make_float2(v10, v11);
            }
        }
    }
}

// ===========================================================================
// Tensor-core flash attention (fp16 mma.sync, fp32 softmax/accum).
// NEW: 2-buffer cp.async K/V (112.6 KB smem) + launch_bounds(256,2) ->
// TWO CTAs/SM. ldsm/mma interleaved in S and PV loops to keep live
// registers under the forced 128-reg cap (same mma order -> bit-identical).
// ===========================================================================
#define FQ 128
#define FK 64
#define QSW 68                       // Q/K/V row stride in words (136 halves)
#define TILE_WORDS (FK * QSW)        // 4352

#define OFF_Q   0
#define OFF_KV  (FQ * QSW)                       // 8704
#define OFF_MSK (OFF_KV + 4 * TILE_WORDS)        // 26112
#define FLASH_SMEM_BYTES ((OFF_MSK + TS) * 4)    // 112640

__device__ __forceinline__ void flash_load_kv(const __half* __restrict__ K,
                                              const __half* __restrict__ V,
                                              uint32_t kvbase, int buf,
                                              size_t base, int k0, int tid) {
    uint32_t kb = kvbase + buf * 2 * TILE_WORDS * 4;
    uint32_t vb = kb + TILE_WORDS * 4;
#pragma unroll
    for (int r = 0; r < 4; r++) {        // K: 64 rows x 16 x 16B
        int idx = r * 256 + tid;
        int row = idx >> 4, q = idx & 15;
        cpasync16(kb + (row * QSW + q * 4) * 4,
                  K + base + (size_t)(k0 + row) * DM + q * 8);
    }
#pragma unroll
    for (int r = 0; r < 4; r++) {        // V: 64 rows x 16 x 16B
        int idx = r * 256 + tid;
        int row = idx >> 4, q = idx & 15;
        cpasync16(vb + (row * QSW + q * 4) * 4,
                  V + base + (size_t)(k0 + row) * DM + q * 8);
    }
    CP_COMMIT();
}

__global__ __launch_bounds__(256, 2)
void flash_f16_kernel(const __half* __restrict__ Q, const __half* __restrict__ K,
                      const __half* __restrict__ V, const int* __restrict__ mask,
                      __half* __restrict__ O)
{
    extern __shared__ uint32_t smw[];
    uint32_t* Qs = smw + OFF_Q;
    int*      msk = (int*)(smw + OFF_MSK);

    const int tid = threadIdx.x;
    const int wid = tid >> 5;
    const int lane = tid & 31;
    const int g = lane >> 2;
    const int tg = lane & 3;
    const int b = blockIdx.x >> 4;
    const int h = blockIdx.x & 15;
    const int q0 = blockIdx.y * FQ;
    const size_t base = (size_t)b * TS * DM + (size_t)h * HD;
    const float scale = 0.08838834764831845f;
    const int qr = wid * 16;

    const int a_mrow = ((lane >> 3) & 1) * 8 + (lane & 7);   // Q (non-trans)
    const int a_kw   = ((lane >> 4) & 1) * 4;
    const int b_nrow = ((lane >> 4) & 1) * 8 + (lane & 7);   // K (non-trans)
    const int b_kw   = ((lane >> 3) & 1) * 4;
    const int v_row  = ((lane >> 3) & 1) * 8 + (lane & 7);   // V (trans): key row
    const int v_cw   = ((lane >> 4) & 1) * 4;                // V: d col words

    const uint32_t Qbase  = smem_u32(Qs);
    const uint32_t KVbase = smem_u32(smw + OFF_KV);

    // Prologue: Q via cp.async + K/V tile 0 into buffer 0; mask once
#pragma unroll
    for (int r = 0; r < 8; r++) {
        int idx = r * 256 + tid;
        int row = idx >> 4, q = idx & 15;
        cpasync16(Qbase + (uint32_t)(row * QSW + q * 4) * 4,
                  Q + base + (size_t)(q0 + row) * DM + q * 8);
    }
    flash_load_kv(K, V, KVbase, 0, base, 0, tid);   // commits Q + tile0
    for (int i = tid; i < TS; i += 256) msk[i] = mask[b * TS + i];

    float m0 = -CUDART_INF_F, m1 = -CUDART_INF_F;
    float l0 = 0.f, l1 = 0.f;
    float co[16][4];
#pragma unroll
    for (int j = 0; j < 16; j++)
#pragma unroll
        for (int v = 0; v < 4; v++) co[j][v] = 0.f;

    const int NT = TS / FK;   // 32
    for (int kt = 0; kt < NT; kt++) {
        const int k0 = kt * FK;
        if (kt + 1 < NT)
            flash_load_kv(K, V, KVbase, (kt + 1) & 1, base, k0 + FK, tid);
        if (kt + 1 < NT) { CP_WAIT(1); } else { CP_WAIT(0); }
        __syncthreads();                 // tile kt ready

        const uint32_t Kbase = KVbase + (uint32_t)((kt & 1) * 2 * TILE_WORDS) * 4;
        const uint32_t Vbase = Kbase + (uint32_t)TILE_WORDS * 4;

        // S = Q . K^T (ldsm/mma interleaved: one K-pair live at a time)
        float cs[8][4];
#pragma unroll
        for (int j = 0; j < 8; j++)
#pragma unroll
            for (int v = 0; v < 4; v++) cs[j][v] = 0.f;

#pragma unroll
        for (int ks = 0; ks < 8; ks++) {
            int kw = ks * 8;
            uint32_t a[4];
            ldsm_x4(a[0], a[1], a[2], a[3],
                    Qbase + (uint32_t)(((qr + a_mrow) * QSW) + a_kw + kw) * 4);
#pragma unroll
            for (int jj = 0; jj < 4; jj++) {
                uint32_t b0[2], b1[2];
                ldsm_x4(b0[0], b0[1], b1[0], b1[1],
                        Kbase + (uint32_t)(((jj * 16 + b_nrow) * QSW) + b_kw + kw) * 4);
                mma_f16(cs[2 * jj], a, b0);
                mma_f16(cs[2 * jj + 1], a, b1);
            }
        }

        // scale + mask
#pragma unroll
        for (int j = 0; j < 8; j++) {
            int c0 = k0 + j * 8 + 2 * tg;
            int mk0 = msk[c0], mk1 = msk[c0 + 1];
            cs[j][0] = mk0 ? cs[j][0] * scale : -CUDART_INF_F;
            cs[j][1] = mk1 ? cs[j][1] * scale : -CUDART_INF_F;
            cs[j][2] = mk0 ? cs[j][2] * scale : -CUDART_INF_F;
            cs[j][3] = mk1 ? cs[j][3] * scale : -CUDART_INF_F;
        }

        // row max (rows qr+g, qr+g+8); reduce over tg lanes
        float mx0 = -CUDART_INF_F, mx1 = -CUDART_INF_F;
#pragma unroll
        for (int j = 0; j < 8; j++) {
            mx0 = fmaxf(mx0, fmaxf(cs[j][0], cs[j][1]));
            mx1 = fmaxf(mx1, fmaxf(cs[j][2], cs[j][3]));
        }
        mx0 = fmaxf(mx0, __shfl_xor_sync(0xffffffffu, mx0, 1));
        mx0 = fmaxf(mx0, __shfl_xor_sync(0xffffffffu, mx0, 2));
        mx1 = fmaxf(mx1, __shfl_xor_sync(0xffffffffu, mx1, 1));
        mx1 = fmaxf(mx1, __shfl_xor_sync(0xffffffffu, mx1, 2));

        float mn0 = fmaxf(m0, mx0), mn1 = fmaxf(m1, mx1);
        float corr0 = __expf(m0 - mn0), corr1 = __expf(m1 - mn1);
        m0 = mn0; m1 = mn1;

        // P = exp(s-m) -> half(rne), register-resident PV A-fragments
        uint32_t ph0[8], ph1[8];
        float rs0 = 0.f, rs1 = 0.f;
#pragma unroll
        for (int j = 0; j < 8; j++) {
            __half2 h0 = __floats2half2_rn(__expf(cs[j][0] - mn0),
                                           __expf(cs[j][1] - mn0));
            __half2 h1 = __floats2half2_rn(__expf(cs[j][2] - mn1),
                                           __expf(cs[j][3] - mn1));
            ph0[j] = *(uint32_t*)&h0;
            ph1[j] = *(uint32_t*)&h1;
            float2 f0 = __half22float2(h0);
            float2 f1 = __half22float2(h1);
            rs0 += f0.x + f0.y; rs1 += f1.x + f1.y;
        }
        rs0 += __shfl_xor_sync(0xffffffffu, rs0, 1);
        rs0 += __shfl_xor_sync(0xffffffffu, rs0, 2);
        rs1 += __shfl_xor_sync(0xffffffffu, rs1, 1);
        rs1 += __shfl_xor_sync(0xffffffffu, rs1, 2);
        l0 = l0 * corr0 + rs0;
        l1 = l1 * corr1 + rs1;

#pragma unroll
        for (int j = 0; j < 16; j++) {
            co[j][0] *= corr0; co[j][1] *= corr0;
            co[j][2] *= corr1; co[j][3] *= corr1;
        }

        // O += P . V (interleaved: one V-pair live at a time)
#pragma unroll
        for (int ks2 = 0; ks2 < 4; ks2++) {
            uint32_t a[4] = {ph0[2 * ks2], ph1[2 * ks2],
                             ph0[2 * ks2 + 1], ph1[2 * ks2 + 1]};
#pragma unroll
            for (int jj = 0; jj < 8; jj++) {
                uint32_t b0[2], b1[2];
                ldsm_x4_t(b0[0], b0[1], b1[0], b1[1],
                          Vbase + (uint32_t)(((ks2 * 16 + v_row) * QSW) + jj * 8 + v_cw) * 4);
                mma_f16(co[2 * jj], a, b0);
                mma_f16(co[2 * jj + 1], a, b1);
            }
        }

        __syncthreads();   // buffer kt&1 fully read before iter kt+1 overwrites
    }

    // Epilogue: normalize, store half
    float inv0 = 1.f / l0, inv1 = 1.f / l1;
    size_t r0 = (size_t)(q0 + qr + g);
    size_t r1 = r0 + 8;
#pragma unroll
    for (int j2 = 0; j2 < 16; j2++) {
        int col = j2 * 8 + 2 * tg;
        __half2 h0 = __floats2half2_rn(co[j2][0] * inv0, co[j2][1] * inv0);
        __half2 h1 = __floats2half2_rn(co[j2][2] * inv1, co[j2][3] * inv1);
        *(__half2*)&O[base + r0 * DM + col] = h0;
        *(__half2*)&O[base + r1 * DM + col] = h1;
    }
}

// ---------------------------------------------------------------------------
extern "C" void kernel_launch(void* const* d_in, const int* in_sizes, int n_in,
                              void* d_out, int out_size)
{
    const float* x  = (const float*)d_in[0];
    const int* mask = (const int*)d_in[1];
    const float* Wq = (const float*)d_in[2];
    const float* bq = (const float*)d_in[3];
    const float* Wk = (const float*)d_in[4];
    const float* bk = (const float*)d_in[5];
    const float* Wv = (const float*)d_in[6];
    const float* bv = (const float*)d_in[7];
    const float* Wo = (const float*)d_in[8];
    const float* bo = (const float*)d_in[9];
    float* out = (float*)d_out;

    __half *xh, *wh, *qh, *kh, *vh, *ah;
    float* bias3;
    cudaGetSymbolAddress((void**)&xh, g_xh);
    cudaGetSymbolAddress((void**)&wh, g_wh);
    cudaGetSymbolAddress((void**)&qh, g_qh);
    cudaGetSymbolAddress((void**)&kh, g_kh);
    cudaGetSymbolAddress((void**)&vh, g_vh);
    cudaGetSymbolAddress((void**)&ah, g_ah);
    cudaGetSymbolAddress((void**)&bias3, g_bias3);

    cudaFuncSetAttribute(gemm_f16_kernel,
                         cudaFuncAttributeMaxDynamicSharedMemorySize, GEMM_SMEM);
    cudaFuncSetAttribute(flash_f16_kernel,
                         cudaFuncAttributeMaxDynamicSharedMemorySize,
                         FLASH_SMEM_BYTES);

    const int NX4 = MR * DM / 4;
    const int NW4 = DM * DM / 4;

    // fp32 -> fp16 conversion: x + 4 weights in ONE launch; bias concat
    cvt_all_kernel<<<4096, 256>>>(x, Wq, Wk, Wv, Wo, xh, wh, NX4, NW4);
    pack_bias_kernel<<<8, 256>>>(bq, bk, bv, bias3);

    // Fused QKV projection: N = 6144 over concatenated weights
    dim3 qkvgrid(NQKV / BN, MR / BM);  // (48, 64)
    gemm_f16_kernel<<<qkvgrid, GTHREADS, GEMM_SMEM>>>(
        xh, wh, bias3, qh, kh, vh, 1);

    flash_f16_kernel<<<dim3(NB * NHEADS, TS / FQ), 256, FLASH_SMEM_BYTES>>>(
        qh, kh, vh, mask, ah);

    // Final projection (float output)
    dim3 ogrid(DM / BN, MR / BM);      // (16, 64)
    gemm_f16_kernel<<<ogrid, GTHREADS, GEMM_SMEM>>>(
        ah, wh + 3 * (size_t)DM * DM, bo, out, nullptr, nullptr, 0);
}

// round 17
// speedup vs baseline: 1.5762x; 1.0092x over previous
#include <cuda_runtime.h>
#include <cuda_fp16.h>
#include <math_constants.h>
#include <cstdint>

#define DM 2048
#define TS 2048
#define NB 4
#define NHEADS 16
#define HD 128
#define MR (NB * TS)   // 8192 rows
#define NQKV (3 * DM)  // 6144

// Scratch (device-global: no allocations allowed in kernel_launch)
__device__ __half g_xh[MR * DM];
__device__ __half g_wh[4 * DM * DM];
__device__ __half g_qh[MR * DM];
__device__ __half g_kh[MR * DM];
__device__ __half g_vh[MR * DM];
__device__ __half g_ah[MR * DM];
__device__ float  g_bias3[NQKV];

// ===========================================================================
// helpers
// ===========================================================================
__device__ __forceinline__ uint32_t smem_u32(const void* p) {
    uint32_t a;
    asm("{ .reg .u64 t; cvta.to.shared.u64 t, %1; cvt.u32.u64 %0, t; }"
        : "=r"(a) : "l"(p));
    return a;
}

__device__ __forceinline__ void cpasync16(uint32_t s, const void* g) {
    asm volatile("cp.async.cg.shared.global [%0], [%1], 16;" :: "r"(s), "l"(g));
}
#define CP_COMMIT() asm volatile("cp.async.commit_group;" ::: "memory")
#define CP_WAIT(n)  asm volatile("cp.async.wait_group %0;" :: "n"(n) : "memory")

__device__ __forceinline__ void mma_f16(float* c, const uint32_t* a,
                                        const uint32_t* b) {
    asm volatile(
        "mma.sync.aligned.m16n8k16.row.col.f32.f16.f16.f32 "
        "{%0,%1,%2,%3}, {%4,%5,%6,%7}, {%8,%9}, {%0,%1,%2,%3};"
        : "+f"(c[0]), "+f"(c[1]), "+f"(c[2]), "+f"(c[3])
        : "r"(a[0]), "r"(a[1]), "r"(a[2]), "r"(a[3]), "r"(b[0]), "r"(b[1]));
}

__device__ __forceinline__ void ldsm_x4(uint32_t& r0, uint32_t& r1,
                                        uint32_t& r2, uint32_t& r3,
                                        uint32_t addr) {
    asm volatile(
        "ldmatrix.sync.aligned.m8n8.x4.shared.b16 {%0,%1,%2,%3}, [%4];"
        : "=r"(r0), "=r"(r1), "=r"(r2), "=r"(r3) : "r"(addr));
}

__device__ __forceinline__ void ldsm_x4_t(uint32_t& r0, uint32_t& r1,
                                          uint32_t& r2, uint32_t& r3,
                                          uint32_t addr) {
    asm volatile(
        "ldmatrix.sync.aligned.m8n8.x4.trans.shared.b16 {%0,%1,%2,%3}, [%4];"
        : "=r"(r0), "=r"(r1), "=r"(r2), "=r"(r3) : "r"(addr));
}

// ===========================================================================
// fp32 -> fp16 conversion (rne): x + 4 weights in ONE kernel; bias concat
// ===========================================================================
__global__ void cvt_all_kernel(const float* __restrict__ x,
                               const float* __restrict__ w0,
                               const float* __restrict__ w1,
                               const float* __restrict__ w2,
                               const float* __restrict__ w3,
                               __half* __restrict__ xh,
                               __half* __restrict__ wh,
                               int nx4, int nw4) {
    int i = blockIdx.x * blockDim.x + threadIdx.x;
    int stride = gridDim.x * blockDim.x;
    int total = nx4 + 4 * nw4;
    for (; i < total; i += stride) {
        const float* src;
        __half* dst;
        int off;
        if (i < nx4) {
            src = x; dst = xh; off = i;
        } else {
            int j = i - nx4;
            int which = j / nw4;
            off = j - which * nw4;
            src = (which == 0) ? w0 : (which == 1) ? w1
                : (which == 2) ? w2 : w3;
            dst = wh + (size_t)which * DM * DM;
        }
        float4 v = ((const float4*)src)[off];
        __half2 h0 = __floats2half2_rn(v.x, v.y);
        __half2 h1 = __floats2half2_rn(v.z, v.w);
        uint2 o = {*(uint32_t*)&h0, *(uint32_t*)&h1};
        ((uint2*)dst)[off] = o;
    }
}

__global__ void pack_bias_kernel(const float* __restrict__ a,
                                 const float* __restrict__ b,
                                 const float* __restrict__ c,
                                 float* __restrict__ o) {
    int i = blockIdx.x * blockDim.x + threadIdx.x;
    if (i < DM) {
        o[i] = a[i];
        o[i + DM] = b[i];
        o[i + 2 * DM] = c[i];
    }
}

// ===========================================================================
// fp16 mma.sync GEMM (ldmatrix fragments, 2 CTAs/SM, single-barrier 3-slot
// cp.async ring). Fused QKV epilogue by (bn >> 11).
// qmul: extra multiplier applied to the C0 (q) output when outHalf
// (folds attention scale * log2e into q so flash softmax runs in exp2
// domain with no per-element scale multiply).
// ===========================================================================
#define BM 128
#define BN 128
#define BKH 64
#define RSW 36                                  // row stride in 4B words
#define STAGE_WORDS ((BM + BN) * RSW)           // 9216
#define GEMM_SMEM (3 * STAGE_WORDS * 4)         // 110592
#define GTHREADS 256

__device__ __forceinline__ void load_chunk_h(const __half* __restrict__ A,
                                             const __half* __restrict__ W,
                                             uint32_t base, int slot,
                                             int bm, int bn, int k0, int tid) {
    uint32_t sa = base + slot * STAGE_WORDS * 4;
#pragma unroll
    for (int r = 0; r < 4; r++) {          // A: 128 rows x 8 x 16B
        int idx = r * GTHREADS + tid;
        int row = idx >> 3, q = idx & 7;
        cpasync16(sa + (row * RSW + q * 4) * 4,
                  A + (size_t)(bm + row) * DM + k0 + q * 8);
    }
    uint32_t sb = sa + BM * RSW * 4;
#pragma unroll
    for (int r = 0; r < 4; r++) {          // B: 128 rows x 8 x 16B
        int idx = r * GTHREADS + tid;
        int row = idx >> 3, q = idx & 7;
        cpasync16(sb + (row * RSW + q * 4) * 4,
                  W + (size_t)(bn + row) * DM + k0 + q * 8);
    }
    CP_COMMIT();
}

__global__ __launch_bounds__(GTHREADS, 2)
void gemm_f16_kernel(const __half* __restrict__ A,
                     const __half* __restrict__ W,
                     const float* __restrict__ bias,
                     void* __restrict__ C0,
                     void* __restrict__ C1,
                     void* __restrict__ C2,
                     int outHalf, float qmul)
{
    extern __shared__ uint32_t smw[];

    const int tid = threadIdx.x;
    const int bm = blockIdx.y * BM;
    const int bn = blockIdx.x * BN;
    const int wid = tid >> 5;
    const int lane = tid & 31;
    const int wm = wid & 1;
    const int wn = wid >> 1;
    const int g = lane >> 2;
    const int tg = lane & 3;
    uint32_t base = smem_u32(smw);

    const int a_row = wm * 64 + ((lane >> 3) & 1) * 8 + (lane & 7);
    const int a_kw  = ((lane >> 4) & 1) * 4;
    const int b_row = wn * 32 + ((lane >> 4) & 1) * 8 + (lane & 7);
    const int b_kw  = ((lane >> 3) & 1) * 4;

    float c[4][4][4];
#pragma unroll
    for (int i = 0; i < 4; i++)
#pragma unroll
        for (int j = 0; j < 4; j++)
#pragma unroll
            for (int v = 0; v < 4; v++) c[i][j][v] = 0.f;

    load_chunk_h(A, W, base, 0, bm, bn, 0 * BKH, tid);
    load_chunk_h(A, W, base, 1, bm, bn, 1 * BKH, tid);

    const int NCHUNK = DM / BKH;    // 32
    for (int k = 0; k < NCHUNK; k++) {
        if (k + 1 < NCHUNK) { CP_WAIT(1); } else { CP_WAIT(0); }
        __syncthreads();
        if (k + 2 < NCHUNK)
            load_chunk_h(A, W, base, (k + 2) % 3, bm, bn, (k + 2) * BKH, tid);

        int slot = k % 3;
        uint32_t Abase = base + slot * STAGE_WORDS * 4;
        uint32_t Bbase = Abase + BM * RSW * 4;

#pragma unroll
        for (int kw = 0; kw < 32; kw += 8) {
            uint32_t a[4][4], b[4][2];
#pragma unroll
            for (int i = 0; i < 4; i++)
                ldsm_x4(a[i][0], a[i][1], a[i][2], a[i][3],
                        Abase + (uint32_t)(((a_row + i * 16) * RSW) + a_kw + kw) * 4);
#pragma unroll
            for (int jj = 0; jj < 2; jj++)
                ldsm_x4(b[2 * jj][0], b[2 * jj][1], b[2 * jj + 1][0], b[2 * jj + 1][1],
                        Bbase + (uint32_t)(((b_row + jj * 16) * RSW) + b_kw + kw) * 4);
#pragma unroll
            for (int i = 0; i < 4; i++)
#pragma unroll
                for (int j = 0; j < 4; j++)
                    mma_f16(c[i][j], a[i], b[j]);
        }
    }

    const int which = bn >> 11;
    void* Csel = (which == 0) ? C0 : ((which == 1) ? C1 : C2);
    const float om = (outHalf && which == 0) ? qmul : 1.f;

#pragma unroll
    for (int j = 0; j < 4; j++) {
        int col = bn + wn * 32 + j * 8 + 2 * tg;
        int coll = col & (DM - 1);
        float b0 = bias[col], b1 = bias[col + 1];
#pragma unroll
        for (int i = 0; i < 4; i++) {
            int row0 = bm + wm * 64 + i * 16 + g;
            float v00 = (c[i][j][0] + b0) * om, v01 = (c[i][j][1] + b1) * om;
            float v10 = (c[i][j][2] + b0) * om, v11 = (c[i][j][3] + b1) * om;
            if (outHalf) {
                __half* C = (__half*)Csel;
                __half2 h0 = __floats2half2_rn(v00, v01);
                __half2 h1 = __floats2half2_rn(v10, v11);
                *(__half2*)&C[(size_t)row0 * DM + coll] = h0;
                *(__half2*)&C[(size_t)(row0 + 8) * DM + coll] = h1;
            } else {
                float* C = (float*)Csel;
                *(float2*)&C[(size_t)row0 * DM + coll] = make_float2(v00, v01);
                *(float2*)&C[(size_t)(row0 + 8) * DM + coll] = make_float2(v10, v11);
            }
        }
    }
}

// ===========================================================================
// Tensor-core flash attention (fp16 mma.sync, fp32 softmax/accum).
// q is pre-scaled by (1/sqrt(hd))*log2e in the GEMM epilogue, so S arrives
// in the exp2 domain: P = exp2(s - m), corr = exp2(m_old - m_new), mask is
// a pure select. 2-buffer cp.async K/V, 2 CTAs/SM, ldsm/mma interleaved.
// ===========================================================================
#define FQ 128
#define FK 64
#define QSW 68                       // Q/K/V row stride in words (136 halves)
#define TILE_WORDS (FK * QSW)        // 4352

#define OFF_Q   0
#define OFF_KV  (FQ * QSW)                       // 8704
#define OFF_MSK (OFF_KV + 4 * TILE_WORDS)        // 26112
#define FLASH_SMEM_BYTES ((OFF_MSK + TS) * 4)    // 112640

__device__ __forceinline__ void flash_load_kv(const __half* __restrict__ K,
                                              const __half* __restrict__ V,
                                              uint32_t kvbase, int buf,
                                              size_t base, int k0, int tid) {
    uint32_t kb = kvbase + buf * 2 * TILE_WORDS * 4;
    uint32_t vb = kb + TILE_WORDS * 4;
#pragma unroll
    for (int r = 0; r < 4; r++) {        // K: 64 rows x 16 x 16B
        int idx = r * 256 + tid;
        int row = idx >> 4, q = idx & 15;
        cpasync16(kb + (row * QSW + q * 4) * 4,
                  K + base + (size_t)(k0 + row) * DM + q * 8);
    }
#pragma unroll
    for (int r = 0; r < 4; r++) {        // V: 64 rows x 16 x 16B
        int idx = r * 256 + tid;
        int row = idx >> 4, q = idx & 15;
        cpasync16(vb + (row * QSW + q * 4) * 4,
                  V + base + (size_t)(k0 + row) * DM + q * 8);
    }
    CP_COMMIT();
}

__global__ __launch_bounds__(256, 2)
void flash_f16_kernel(const __half* __restrict__ Q, const __half* __restrict__ K,
                      const __half* __restrict__ V, const int* __restrict__ mask,
                      __half* __restrict__ O)
{
    extern __shared__ uint32_t smw[];
    uint32_t* Qs = smw + OFF_Q;
    int*      msk = (int*)(smw + OFF_MSK);

    const int tid = threadIdx.x;
    const int wid = tid >> 5;
    const int lane = tid & 31;
    const int g = lane >> 2;
    const int tg = lane & 3;
    const int b = blockIdx.x >> 4;
    const int h = blockIdx.x & 15;
    const int q0 = blockIdx.y * FQ;
    const size_t base = (size_t)b * TS * DM + (size_t)h * HD;
    const int qr = wid * 16;

    const int a_mrow = ((lane >> 3) & 1) * 8 + (lane & 7);   // Q (non-trans)
    const int a_kw   = ((lane >> 4) & 1) * 4;
    const int b_nrow = ((lane >> 4) & 1) * 8 + (lane & 7);   // K (non-trans)
    const int b_kw   = ((lane >> 3) & 1) * 4;
    const int v_row  = ((lane >> 3) & 1) * 8 + (lane & 7);   // V (trans): key row
    const int v_cw   = ((lane >> 4) & 1) * 4;                // V: d col words

    const uint32_t Qbase  = smem_u32(Qs);
    const uint32_t KVbase = smem_u32(smw + OFF_KV);

    // Prologue: Q via cp.async + K/V tile 0 into buffer 0; mask once
#pragma unroll
    for (int r = 0; r < 8; r++) {
        int idx = r * 256 + tid;
        int row = idx >> 4, q = idx & 15;
        cpasync16(Qbase + (uint32_t)(row * QSW + q * 4) * 4,
                  Q + base + (size_t)(q0 + row) * DM + q * 8);
    }
    flash_load_kv(K, V, KVbase, 0, base, 0, tid);   // commits Q + tile0
    for (int i = tid; i < TS; i += 256) msk[i] = mask[b * TS + i];

    float m0 = -CUDART_INF_F, m1 = -CUDART_INF_F;
    float l0 = 0.f, l1 = 0.f;
    float co[16][4];
#pragma unroll
    for (int j = 0; j < 16; j++)
#pragma unroll
        for (int v = 0; v < 4; v++) co[j][v] = 0.f;

    const int NT = TS / FK;   // 32
    for (int kt = 0; kt < NT; kt++) {
        const int k0 = kt * FK;
        if (kt + 1 < NT)
            flash_load_kv(K, V, KVbase, (kt + 1) & 1, base, k0 + FK, tid);
        if (kt + 1 < NT) { CP_WAIT(1); } else { CP_WAIT(0); }
        __syncthreads();                 // tile kt ready

        const uint32_t Kbase = KVbase + (uint32_t)((kt & 1) * 2 * TILE_WORDS) * 4;
        const uint32_t Vbase = Kbase + (uint32_t)TILE_WORDS * 4;

        // S = Q . K^T  (already in exp2 domain; ldsm/mma interleaved)
        float cs[8][4];
#pragma unroll
        for (int j = 0; j < 8; j++)
#pragma unroll
            for (int v = 0; v < 4; v++) cs[j][v] = 0.f;

#pragma unroll
        for (int ks = 0; ks < 8; ks++) {
            int kw = ks * 8;
            uint32_t a[4];
            ldsm_x4(a[0], a[1], a[2], a[3],
                    Qbase + (uint32_t)(((qr + a_mrow) * QSW) + a_kw + kw) * 4);
#pragma unroll
            for (int jj = 0; jj < 4; jj++) {
                uint32_t b0[2], b1[2];
                ldsm_x4(b0[0], b0[1], b1[0], b1[1],
                        Kbase + (uint32_t)(((jj * 16 + b_nrow) * QSW) + b_kw + kw) * 4);
                mma_f16(cs[2 * jj], a, b0);
                mma_f16(cs[2 * jj + 1], a, b1);
            }
        }

        // mask (pure select; no scale multiply needed)
#pragma unroll
        for (int j = 0; j < 8; j++) {
            int c0 = k0 + j * 8 + 2 * tg;
            int mk0 = msk[c0], mk1 = msk[c0 + 1];
            cs[j][0] = mk0 ? cs[j][0] : -CUDART_INF_F;
            cs[j][1] = mk1 ? cs[j][1] : -CUDART_INF_F;
            cs[j][2] = mk0 ? cs[j][2] : -CUDART_INF_F;
            cs[j][3] = mk1 ? cs[j][3] : -CUDART_INF_F;
        }

        // row max (rows qr+g, qr+g+8); reduce over tg lanes
        float mx0 = -CUDART_INF_F, mx1 = -CUDART_INF_F;
#pragma unroll
        for (int j = 0; j < 8; j++) {
            mx0 = fmaxf(mx0, fmaxf(cs[j][0], cs[j][1]));
            mx1 = fmaxf(mx1, fmaxf(cs[j][2], cs[j][3]));
        }
        mx0 = fmaxf(mx0, __shfl_xor_sync(0xffffffffu, mx0, 1));
        mx0 = fmaxf(mx0, __shfl_xor_sync(0xffffffffu, mx0, 2));
        mx1 = fmaxf(mx1, __shfl_xor_sync(0xffffffffu, mx1, 1));
        mx1 = fmaxf(mx1, __shfl_xor_sync(0xffffffffu, mx1, 2));

        float mn0 = fmaxf(m0, mx0), mn1 = fmaxf(m1, mx1);
        float corr0 = exp2f(m0 - mn0), corr1 = exp2f(m1 - mn1);
        m0 = mn0; m1 = mn1;

        // P = exp2(s-m) -> half(rne), register-resident PV A-fragments
        uint32_t ph0[8], ph1[8];
        float rs0 = 0.f, rs1 = 0.f;
#pragma unroll
        for (int j = 0; j < 8; j++) {
            __half2 h0 = __floats2half2_rn(exp2f(cs[j][0] - mn0),
                                           exp2f(cs[j][1] - mn0));
            __half2 h1 = __floats2half2_rn(exp2f(cs[j][2] - mn1),
                                           exp2f(cs[j][3] - mn1));
            ph0[j] = *(uint32_t*)&h0;
            ph1[j] = *(uint32_t*)&h1;
            float2 f0 = __half22float2(h0);
            float2 f1 = __half22float2(h1);
            rs0 += f0.x + f0.y; rs1 += f1.x + f1.y;
        }
        rs0 += __shfl_xor_sync(0xffffffffu, rs0, 1);
        rs0 += __shfl_xor_sync(0xffffffffu, rs0, 2);
        rs1 += __shfl_xor_sync(0xffffffffu, rs1, 1);
        rs1 += __shfl_xor_sync(0xffffffffu, rs1, 2);
        l0 = l0 * corr0 + rs0;
        l1 = l1 * corr1 + rs1;

#pragma unroll
        for (int j = 0; j < 16; j++) {
            co[j][0] *= corr0; co[j][1] *= corr0;
            co[j][2] *= corr1; co[j][3] *= corr1;
        }

        // O += P . V (interleaved: one V-pair live at a time)
#pragma unroll
        for (int ks2 = 0; ks2 < 4; ks2++) {
            uint32_t a[4] = {ph0[2 * ks2], ph1[2 * ks2],
                             ph0[2 * ks2 + 1], ph1[2 * ks2 + 1]};
#pragma unroll
            for (int jj = 0; jj < 8; jj++) {
                uint32_t b0[2], b1[2];
                ldsm_x4_t(b0[0], b0[1], b1[0], b1[1],
                          Vbase + (uint32_t)(((ks2 * 16 + v_row) * QSW) + jj * 8 + v_cw) * 4);
                mma_f16(co[2 * jj], a, b0);
                mma_f16(co[2 * jj + 1], a, b1);
            }
        }

        __syncthreads();   // buffer kt&1 fully read before iter kt+1 overwrites
    }

    // Epilogue: normalize, store half
    float inv0 = 1.f / l0, inv1 = 1.f / l1;
    size_t r0 = (size_t)(q0 + qr + g);
    size_t r1 = r0 + 8;
#pragma unroll
    for (int j2 = 0; j2 < 16; j2++) {
        int col = j2 * 8 + 2 * tg;
        __half2 h0 = __floats2half2_rn(co[j2][0] * inv0, co[j2][1] * inv0);
        __half2 h1 = __floats2half2_rn(co[j2][2] * inv1, co[j2][3] * inv1);
        *(__half2*)&O[base + r0 * DM + col] = h0;
        *(__half2*)&O[base + r1 * DM + col] = h1;
    }
}

// ---------------------------------------------------------------------------
extern "C" void kernel_launch(void* const* d_in, const int* in_sizes, int n_in,
                              void* d_out, int out_size)
{
    const float* x  = (const float*)d_in[0];
    const int* mask = (const int*)d_in[1];
    const float* Wq = (const float*)d_in[2];
    const float* bq = (const float*)d_in[3];
    const float* Wk = (const float*)d_in[4];
    const float* bk = (const float*)d_in[5];
    const float* Wv = (const float*)d_in[6];
    const float* bv = (const float*)d_in[7];
    const float* Wo = (const float*)d_in[8];
    const float* bo = (const float*)d_in[9];
    float* out = (float*)d_out;

    __half *xh, *wh, *qh, *kh, *vh, *ah;
    float* bias3;
    cudaGetSymbolAddress((void**)&xh, g_xh);
    cudaGetSymbolAddress((void**)&wh, g_wh);
    cudaGetSymbolAddress((void**)&qh, g_qh);
    cudaGetSymbolAddress((void**)&kh, g_kh);
    cudaGetSymbolAddress((void**)&vh, g_vh);
    cudaGetSymbolAddress((void**)&ah, g_ah);
    cudaGetSymbolAddress((void**)&bias3, g_bias3);

    cudaFuncSetAttribute(gemm_f16_kernel,
                         cudaFuncAttributeMaxDynamicSharedMemorySize, GEMM_SMEM);
    cudaFuncSetAttribute(flash_f16_kernel,
                         cudaFuncAttributeMaxDynamicSharedMemorySize,
                         FLASH_SMEM_BYTES);

    const int NX4 = MR * DM / 4;
    const int NW4 = DM * DM / 4;

    // q pre-multiplier: (1/sqrt(hd)) * log2(e)  -> softmax in exp2 domain
    const float QMUL = 0.08838834764831845f * 1.4426950408889634f;

    // fp32 -> fp16 conversion: x + 4 weights in ONE launch; bias concat
    cvt_all_kernel<<<4096, 256>>>(x, Wq, Wk, Wv, Wo, xh, wh, NX4, NW4);
    pack_bias_kernel<<<8, 256>>>(bq, bk, bv, bias3);

    // Fused QKV projection: N = 6144 over concatenated weights
    dim3 qkvgrid(NQKV / BN, MR / BM);  // (48, 64)
    gemm_f16_kernel<<<qkvgrid, GTHREADS, GEMM_SMEM>>>(
        xh, wh, bias3, qh, kh, vh, 1, QMUL);

    flash_f16_kernel<<<dim3(NB * NHEADS, TS / FQ), 256, FLASH_SMEM_BYTES>>>(
        qh, kh, vh, mask, ah);

    // Final projection (float output)
    dim3 ogrid(DM / BN, MR / BM);      // (16, 64)
    gemm_f16_kernel<<<ogrid, GTHREADS, GEMM_SMEM>>>(
        ah, wh + 3 * (size_t)DM * DM, bo, out, nullptr, nullptr, 0, 1.f);
}